// round 2
// baseline (speedup 1.0000x reference)
#include <cuda_runtime.h>
#include <math.h>

#define BB 8
#define NN 512
#define DD 512
#define HH 8
#define DH 64
#define DI 512            // DIM_INNER
#define N3 1536           // 3*N concatenated keys
#define SCALE 0.125f
#define NEGV -1e9f

// Scratch (device globals: allocation-free per harness rules)
__device__ float g_Q[3ull * BB * HH * NN * DH];   // [mod][b][h][n][d], pre-scaled
__device__ float g_K[(size_t)BB * HH * N3 * DH];  // [b][h][3n][d]
__device__ float g_V[(size_t)BB * HH * N3 * DH];
__device__ float g_O[3ull * BB * NN * DI];        // [mod][b][n][h*d]

// ---------------------------------------------------------------------------
// Kernel 1: QKV GEMM  X[4096,512] @ W[512,1536] with head-split scatter.
// grid (24, 64, 3), block 256. Tile 64x64, k-chunk 16, 4x4 per thread.
// ---------------------------------------------------------------------------
__global__ void qkv_gemm_kernel(const float* __restrict__ x0,
                                const float* __restrict__ x1,
                                const float* __restrict__ x2,
                                const float* __restrict__ w0,
                                const float* __restrict__ w1,
                                const float* __restrict__ w2) {
    const int mod = blockIdx.z;
    const float* __restrict__ X = (mod == 0) ? x0 : (mod == 1) ? x1 : x2;
    const float* __restrict__ W = (mod == 0) ? w0 : (mod == 1) ? w1 : w2;

    __shared__ float Xs[64][17];
    __shared__ float Ws[16][68];

    const int tid = threadIdx.x;
    const int ty = tid >> 4, tx = tid & 15;
    const int rowbase = blockIdx.y * 64;
    const int colbase = blockIdx.x * 64;

    float acc[4][4];
#pragma unroll
    for (int i = 0; i < 4; i++)
#pragma unroll
        for (int j = 0; j < 4; j++) acc[i][j] = 0.f;

    for (int k0 = 0; k0 < 512; k0 += 16) {
        {
            int r = tid >> 2, c = (tid & 3) * 4;
            float4 v = *(const float4*)(X + (size_t)(rowbase + r) * 512 + k0 + c);
            Xs[r][c] = v.x; Xs[r][c + 1] = v.y; Xs[r][c + 2] = v.z; Xs[r][c + 3] = v.w;
            int r2 = tid >> 4, c2 = (tid & 15) * 4;
            float4 w = *(const float4*)(W + (size_t)(k0 + r2) * 1536 + colbase + c2);
            Ws[r2][c2] = w.x; Ws[r2][c2 + 1] = w.y; Ws[r2][c2 + 2] = w.z; Ws[r2][c2 + 3] = w.w;
        }
        __syncthreads();
#pragma unroll
        for (int kk = 0; kk < 16; kk++) {
            float a[4], b[4];
#pragma unroll
            for (int i = 0; i < 4; i++) a[i] = Xs[ty * 4 + i][kk];
#pragma unroll
            for (int j = 0; j < 4; j++) b[j] = Ws[kk][tx * 4 + j];
#pragma unroll
            for (int i = 0; i < 4; i++)
#pragma unroll
                for (int j = 0; j < 4; j++) acc[i][j] = fmaf(a[i], b[j], acc[i][j]);
        }
        __syncthreads();
    }

    // Scatter epilogue
#pragma unroll
    for (int i = 0; i < 4; i++) {
        int gr = rowbase + ty * 4 + i;          // 0..4095
        int b = gr >> 9, n = gr & 511;
#pragma unroll
        for (int j = 0; j < 4; j++) {
            int gc = colbase + tx * 4 + j;      // 0..1535
            float v = acc[i][j];
            if (gc < 512) {
                int h = gc >> 6, dd = gc & 63;
                g_Q[((((size_t)mod * BB + b) * HH + h) * NN + n) * DH + dd] = v * SCALE;
            } else if (gc < 1024) {
                int c2 = gc - 512; int h = c2 >> 6, dd = c2 & 63;
                g_K[(((size_t)b * HH + h) * N3 + mod * NN + n) * DH + dd] = v;
            } else {
                int c2 = gc - 1024; int h = c2 >> 6, dd = c2 & 63;
                g_V[(((size_t)b * HH + h) * N3 + mod * NN + n) * DH + dd] = v;
            }
        }
    }
}

// ---------------------------------------------------------------------------
// Kernel 2: Flash attention. grid (8, 64, 3) = (qtile, b*H+h, mod), block 256.
// ---------------------------------------------------------------------------
#define ATT_SMEM (4 * 64 * 65 * 4 + 3 * 64 * 4 + 64 * 4)

__global__ void attn_kernel(const int* __restrict__ m0,
                            const int* __restrict__ m1,
                            const int* __restrict__ m2) {
    extern __shared__ float sm[];
    float* Qs = sm;                   // 64*65
    float* Ks = Qs + 64 * 65;
    float* Vs = Ks + 64 * 65;
    float* Ss = Vs + 64 * 65;
    float* mrow = Ss + 64 * 65;       // 64
    float* lrow = mrow + 64;
    float* arow = lrow + 64;
    int*   qm   = (int*)(arow + 64);

    const int mod = blockIdx.z;
    const int bh = blockIdx.y;              // b*H + h
    const int b = bh >> 3, h = bh & 7;
    const int qt = blockIdx.x;
    const int tid = threadIdx.x;
    const int ty = tid >> 4, tx = tid & 15;

    const int* __restrict__ M = (mod == 0) ? m0 : (mod == 1) ? m1 : m2;

    // Load Q tile (pre-scaled)
    const float* Qg = g_Q + ((((size_t)mod * BB + b) * HH + h) * NN + qt * 64) * DH;
#pragma unroll
    for (int v = tid; v < 1024; v += 256) {
        int r = v >> 4, c = (v & 15) * 4;
        float4 q4 = *(const float4*)(Qg + r * 64 + c);
        Qs[r * 65 + c] = q4.x; Qs[r * 65 + c + 1] = q4.y;
        Qs[r * 65 + c + 2] = q4.z; Qs[r * 65 + c + 3] = q4.w;
    }
    if (tid < 64) {
        qm[tid] = M[b * NN + qt * 64 + tid];
        mrow[tid] = -1e30f;
        lrow[tid] = 0.f;
    }

    float oacc[4][4];
#pragma unroll
    for (int i = 0; i < 4; i++)
#pragma unroll
        for (int j = 0; j < 4; j++) oacc[i][j] = 0.f;

    const float* Kg = g_K + (size_t)bh * N3 * DH;
    const float* Vg = g_V + (size_t)bh * N3 * DH;

    __syncthreads();

    for (int kt = 0; kt < 24; kt++) {
        // Load K,V tiles
#pragma unroll
        for (int v = tid; v < 1024; v += 256) {
            int r = v >> 4, c = (v & 15) * 4;
            float4 k4 = *(const float4*)(Kg + (size_t)(kt * 64 + r) * 64 + c);
            Ks[r * 65 + c] = k4.x; Ks[r * 65 + c + 1] = k4.y;
            Ks[r * 65 + c + 2] = k4.z; Ks[r * 65 + c + 3] = k4.w;
            float4 v4 = *(const float4*)(Vg + (size_t)(kt * 64 + r) * 64 + c);
            Vs[r * 65 + c] = v4.x; Vs[r * 65 + c + 1] = v4.y;
            Vs[r * 65 + c + 2] = v4.z; Vs[r * 65 + c + 3] = v4.w;
        }
        __syncthreads();

        // S = Q K^T  (Q pre-scaled)
        float sacc[4][4];
#pragma unroll
        for (int i = 0; i < 4; i++)
#pragma unroll
            for (int j = 0; j < 4; j++) sacc[i][j] = 0.f;
#pragma unroll 8
        for (int kk = 0; kk < 64; kk++) {
            float a[4], bv[4];
#pragma unroll
            for (int i = 0; i < 4; i++) a[i] = Qs[(ty * 4 + i) * 65 + kk];
#pragma unroll
            for (int j = 0; j < 4; j++) bv[j] = Ks[(tx * 4 + j) * 65 + kk];
#pragma unroll
            for (int i = 0; i < 4; i++)
#pragma unroll
                for (int j = 0; j < 4; j++) sacc[i][j] = fmaf(a[i], bv[j], sacc[i][j]);
        }
#pragma unroll
        for (int i = 0; i < 4; i++)
#pragma unroll
            for (int j = 0; j < 4; j++)
                Ss[(ty * 4 + i) * 65 + tx * 4 + j] = sacc[i][j];
        __syncthreads();

        // Online softmax per query row (threads 0..63)
        if (tid < 64) {
            const bool on = (qm[tid] != 0);
            float* srow = Ss + tid * 65;
            float mold = mrow[tid];
            float mx = mold;
            if (on) {
#pragma unroll 8
                for (int j = 0; j < 64; j++) mx = fmaxf(mx, srow[j]);
            } else {
                mx = fmaxf(mold, NEGV);
            }
            float alpha = __expf(mold - mx);
            float sum = 0.f;
#pragma unroll 8
            for (int j = 0; j < 64; j++) {
                float sv = on ? srow[j] : NEGV;
                float p = __expf(sv - mx);
                srow[j] = p;
                sum += p;
            }
            lrow[tid] = lrow[tid] * alpha + sum;
            mrow[tid] = mx;
            arow[tid] = alpha;
        }
        __syncthreads();

        // O = alpha*O + P V
        float al[4];
#pragma unroll
        for (int i = 0; i < 4; i++) al[i] = arow[ty * 4 + i];
#pragma unroll
        for (int i = 0; i < 4; i++)
#pragma unroll
            for (int j = 0; j < 4; j++) oacc[i][j] *= al[i];
#pragma unroll 8
        for (int k = 0; k < 64; k++) {
            float p[4], vv[4];
#pragma unroll
            for (int i = 0; i < 4; i++) p[i] = Ss[(ty * 4 + i) * 65 + k];
#pragma unroll
            for (int j = 0; j < 4; j++) vv[j] = Vs[k * 65 + tx * 4 + j];
#pragma unroll
            for (int i = 0; i < 4; i++)
#pragma unroll
                for (int j = 0; j < 4; j++) oacc[i][j] = fmaf(p[i], vv[j], oacc[i][j]);
        }
        __syncthreads();
    }

    // Epilogue: normalize and write to [mod][b][n][h*64+d]
#pragma unroll
    for (int i = 0; i < 4; i++) {
        int q = ty * 4 + i;
        float linv = 1.0f / lrow[q];
#pragma unroll
        for (int j = 0; j < 4; j++) {
            int dd = tx * 4 + j;
            g_O[(((size_t)mod * BB + b) * NN + qt * 64 + q) * DI + h * 64 + dd] =
                oacc[i][j] * linv;
        }
    }
}

// ---------------------------------------------------------------------------
// Kernel 3: Output GEMM  O[4096,512] @ Wout[512,512] -> d_out.
// grid (8, 64, 3), block 256.
// ---------------------------------------------------------------------------
__global__ void out_gemm_kernel(const float* __restrict__ w0,
                                const float* __restrict__ w1,
                                const float* __restrict__ w2,
                                float* __restrict__ out) {
    const int mod = blockIdx.z;
    const float* __restrict__ X = g_O + (size_t)mod * 4096 * 512;
    const float* __restrict__ W = (mod == 0) ? w0 : (mod == 1) ? w1 : w2;
    float* __restrict__ O = out + (size_t)mod * 4096 * 512;

    __shared__ float Xs[64][17];
    __shared__ float Ws[16][68];

    const int tid = threadIdx.x;
    const int ty = tid >> 4, tx = tid & 15;
    const int rowbase = blockIdx.y * 64;
    const int colbase = blockIdx.x * 64;

    float acc[4][4];
#pragma unroll
    for (int i = 0; i < 4; i++)
#pragma unroll
        for (int j = 0; j < 4; j++) acc[i][j] = 0.f;

    for (int k0 = 0; k0 < 512; k0 += 16) {
        {
            int r = tid >> 2, c = (tid & 3) * 4;
            float4 v = *(const float4*)(X + (size_t)(rowbase + r) * 512 + k0 + c);
            Xs[r][c] = v.x; Xs[r][c + 1] = v.y; Xs[r][c + 2] = v.z; Xs[r][c + 3] = v.w;
            int r2 = tid >> 4, c2 = (tid & 15) * 4;
            float4 w = *(const float4*)(W + (size_t)(k0 + r2) * 512 + colbase + c2);
            Ws[r2][c2] = w.x; Ws[r2][c2 + 1] = w.y; Ws[r2][c2 + 2] = w.z; Ws[r2][c2 + 3] = w.w;
        }
        __syncthreads();
#pragma unroll
        for (int kk = 0; kk < 16; kk++) {
            float a[4], b[4];
#pragma unroll
            for (int i = 0; i < 4; i++) a[i] = Xs[ty * 4 + i][kk];
#pragma unroll
            for (int j = 0; j < 4; j++) b[j] = Ws[kk][tx * 4 + j];
#pragma unroll
            for (int i = 0; i < 4; i++)
#pragma unroll
                for (int j = 0; j < 4; j++) acc[i][j] = fmaf(a[i], b[j], acc[i][j]);
        }
        __syncthreads();
    }

#pragma unroll
    for (int i = 0; i < 4; i++) {
        int gr = rowbase + ty * 4 + i;
#pragma unroll
        for (int j = 0; j < 4; j++) {
            int gc = colbase + tx * 4 + j;
            O[(size_t)gr * 512 + gc] = acc[i][j];
        }
    }
}

// ---------------------------------------------------------------------------
// Input order per setup_inputs() dict insertion:
//   0:x0 1:m0 2:Wqkv0 3:Wout0 | 4:x1 5:m1 6:Wqkv1 7:Wout1 | 8:x2 9:m2 10:Wqkv2 11:Wout2
// ---------------------------------------------------------------------------
extern "C" void kernel_launch(void* const* d_in, const int* in_sizes, int n_in,
                              void* d_out, int out_size) {
    const float* x0  = (const float*)d_in[0];
    const int*   m0  = (const int*)d_in[1];
    const float* wq0 = (const float*)d_in[2];
    const float* wo0 = (const float*)d_in[3];
    const float* x1  = (const float*)d_in[4];
    const int*   m1  = (const int*)d_in[5];
    const float* wq1 = (const float*)d_in[6];
    const float* wo1 = (const float*)d_in[7];
    const float* x2  = (const float*)d_in[8];
    const int*   m2  = (const int*)d_in[9];
    const float* wq2 = (const float*)d_in[10];
    const float* wo2 = (const float*)d_in[11];
    float* out = (float*)d_out;

    cudaFuncSetAttribute(attn_kernel, cudaFuncAttributeMaxDynamicSharedMemorySize,
                         ATT_SMEM);

    qkv_gemm_kernel<<<dim3(24, 64, 3), 256>>>(x0, x1, x2, wq0, wq1, wq2);
    attn_kernel<<<dim3(8, 64, 3), 256, ATT_SMEM>>>(m0, m1, m2);
    out_gemm_kernel<<<dim3(8, 64, 3), 256>>>(wo0, wo1, wo2, out);
}

// round 3
// speedup vs baseline: 3.4723x; 3.4723x over previous
#include <cuda_runtime.h>
#include <math.h>

#define BB 8
#define NN 512
#define HH 8
#define DH 64
#define DI 512
#define N3 1536
#define SCALE 0.125f
#define NEGV -1e9f

// Scratch (device globals; Q/K/V stored pre-rounded to tf32-exact fp32)
__device__ float g_Q[3ull * BB * HH * NN * DH];   // [mod][b][h][n][d], pre-scaled
__device__ float g_K[(size_t)BB * HH * N3 * DH];  // [b][h][3n][d]
__device__ float g_V[(size_t)BB * HH * N3 * DH];
__device__ float g_O[3ull * BB * NN * DI];        // [mod][b][n][h*d]

__device__ __forceinline__ unsigned f2t(float f) {
    unsigned u;
    asm("cvt.rna.tf32.f32 %0, %1;" : "=r"(u) : "f"(f));
    return u;
}
__device__ __forceinline__ float tf32r(float f) { return __uint_as_float(f2t(f)); }

__device__ __forceinline__ void mma8(float d[4], const unsigned a[4], const unsigned b[2]) {
    asm volatile(
        "mma.sync.aligned.m16n8k8.row.col.f32.tf32.tf32.f32 "
        "{%0,%1,%2,%3}, {%4,%5,%6,%7}, {%8,%9}, {%0,%1,%2,%3};"
        : "+f"(d[0]), "+f"(d[1]), "+f"(d[2]), "+f"(d[3])
        : "r"(a[0]), "r"(a[1]), "r"(a[2]), "r"(a[3]), "r"(b[0]), "r"(b[1]));
}

// ---------------------------------------------------------------------------
// Tensor-core GEMM: C[4096, NC] = X[4096,512] @ W[512,NC].
// 128x128 tile, 256 threads (8 warps, 2x4), k-chunk 32, reg-prefetch pipeline.
// EPI=0: QKV scatter epilogue.  EPI=1: direct fp32 store to out.
// ---------------------------------------------------------------------------
#define SA 36
#define SB 132

template <int NC, int EPI>
__global__ void gemm_tc(const float* __restrict__ x0, const float* __restrict__ x1,
                        const float* __restrict__ x2, const float* __restrict__ w0,
                        const float* __restrict__ w1, const float* __restrict__ w2,
                        float* __restrict__ out) {
    __shared__ unsigned Xs[128 * SA];
    __shared__ unsigned Ws[32 * SB];

    const int mod = blockIdx.z;
    const float* __restrict__ X;
    const float* __restrict__ W = (mod == 0) ? w0 : (mod == 1) ? w1 : w2;
    if (EPI == 0) X = (mod == 0) ? x0 : (mod == 1) ? x1 : x2;
    else          X = g_O + (size_t)mod * 4096 * 512;

    const int tid = threadIdx.x;
    const int wid = tid >> 5, lane = tid & 31;
    const int grp = lane >> 2, l4 = lane & 3;
    const int wm = wid >> 2, wn = wid & 3;
    const int rowbase = blockIdx.y * 128;
    const int colbase = blockIdx.x * 128;

    float c[4][4][4];
#pragma unroll
    for (int mt = 0; mt < 4; mt++)
#pragma unroll
        for (int nt = 0; nt < 4; nt++)
#pragma unroll
            for (int e = 0; e < 4; e++) c[mt][nt][e] = 0.f;

    float4 xr[4], wr[4];

    auto ldg = [&](int k0) {
#pragma unroll
        for (int i = 0; i < 4; i++) {
            int v = tid + i * 256;
            int r = v >> 3, c4 = (v & 7) << 2;
            xr[i] = *(const float4*)(X + (size_t)(rowbase + r) * 512 + k0 + c4);
            int r2 = v >> 5, c42 = (v & 31) << 2;
            wr[i] = *(const float4*)(W + (size_t)(k0 + r2) * NC + colbase + c42);
        }
    };
    auto sts = [&]() {
#pragma unroll
        for (int i = 0; i < 4; i++) {
            int v = tid + i * 256;
            int r = v >> 3, c4 = (v & 7) << 2;
            *(uint4*)&Xs[r * SA + c4] =
                make_uint4(f2t(xr[i].x), f2t(xr[i].y), f2t(xr[i].z), f2t(xr[i].w));
            int r2 = v >> 5, c42 = (v & 31) << 2;
            *(uint4*)&Ws[r2 * SB + c42] =
                make_uint4(f2t(wr[i].x), f2t(wr[i].y), f2t(wr[i].z), f2t(wr[i].w));
        }
    };

    ldg(0);
    sts();
    __syncthreads();

    for (int chunk = 0; chunk < 16; chunk++) {
        if (chunk < 15) ldg((chunk + 1) * 32);

#pragma unroll
        for (int k8 = 0; k8 < 4; k8++) {
            unsigned a[4][4];
#pragma unroll
            for (int mt = 0; mt < 4; mt++) {
                int r0 = wm * 64 + mt * 16 + grp;
                a[mt][0] = Xs[r0 * SA + k8 * 8 + l4];
                a[mt][1] = Xs[(r0 + 8) * SA + k8 * 8 + l4];
                a[mt][2] = Xs[r0 * SA + k8 * 8 + l4 + 4];
                a[mt][3] = Xs[(r0 + 8) * SA + k8 * 8 + l4 + 4];
            }
#pragma unroll
            for (int nt = 0; nt < 4; nt++) {
                unsigned b[2];
                int col = wn * 32 + nt * 8 + grp;
                b[0] = Ws[(k8 * 8 + l4) * SB + col];
                b[1] = Ws[(k8 * 8 + l4 + 4) * SB + col];
#pragma unroll
                for (int mt = 0; mt < 4; mt++) mma8(c[mt][nt], a[mt], b);
            }
        }
        __syncthreads();
        if (chunk < 15) {
            sts();
            __syncthreads();
        }
    }

    // Epilogue
#pragma unroll
    for (int mt = 0; mt < 4; mt++) {
        int gr0 = rowbase + wm * 64 + mt * 16 + grp;
        int gr1 = gr0 + 8;
#pragma unroll
        for (int nt = 0; nt < 4; nt++) {
            int gc = colbase + wn * 32 + nt * 8 + l4 * 2;
            if (EPI == 1) {
                *(float2*)(out + ((size_t)mod * 4096 + gr0) * 512 + gc) =
                    make_float2(c[mt][nt][0], c[mt][nt][1]);
                *(float2*)(out + ((size_t)mod * 4096 + gr1) * 512 + gc) =
                    make_float2(c[mt][nt][2], c[mt][nt][3]);
            } else {
#pragma unroll
                for (int e = 0; e < 4; e++) {
                    int gr = (e < 2) ? gr0 : gr1;
                    int gcc = gc + (e & 1);
                    float v = c[mt][nt][e];
                    int b = gr >> 9, n = gr & 511;
                    if (gcc < 512) {
                        int h = gcc >> 6, dd = gcc & 63;
                        g_Q[((((size_t)mod * BB + b) * HH + h) * NN + n) * DH + dd] =
                            tf32r(v * SCALE);
                    } else if (gcc < 1024) {
                        int c2 = gcc - 512, h = c2 >> 6, dd = c2 & 63;
                        g_K[(((size_t)b * HH + h) * N3 + mod * NN + n) * DH + dd] = tf32r(v);
                    } else {
                        int c2 = gcc - 1024, h = c2 >> 6, dd = c2 & 63;
                        g_V[(((size_t)b * HH + h) * N3 + mod * NN + n) * DH + dd] = tf32r(v);
                    }
                }
            }
        }
    }
}

// ---------------------------------------------------------------------------
// Tensor-core flash attention. grid (8 qtiles, 64 bh, 3 mod), 128 threads.
// Warp w handles q-rows [w*16, w*16+16). Q in reg A-frags, S/O in mma accums,
// online softmax in-register, P reshaped C->A frags via quad shuffles.
// ---------------------------------------------------------------------------
#define SK 68
#define SV 72

__global__ void attn_tc(const int* __restrict__ m0, const int* __restrict__ m1,
                        const int* __restrict__ m2) {
    __shared__ unsigned Ks[64 * SK];
    __shared__ unsigned Vs[64 * SV];

    const int mod = blockIdx.z;
    const int bh = blockIdx.y;
    const int b = bh >> 3, h = bh & 7;
    const int qt = blockIdx.x;
    const int tid = threadIdx.x;
    const int wid = tid >> 5, lane = tid & 31;
    const int grp = lane >> 2, l4 = lane & 3;

    const int* __restrict__ M = (mod == 0) ? m0 : (mod == 1) ? m1 : m2;

    const int r0 = wid * 16 + grp;   // within 64-row q tile
    const int r1 = r0 + 8;
    const bool on0 = (M[b * NN + qt * 64 + r0] != 0);
    const bool on1 = (M[b * NN + qt * 64 + r1] != 0);

    // Q A-fragments (g_Q is tf32-exact and pre-scaled)
    const float* Qg = g_Q + ((((size_t)mod * BB + b) * HH + h) * NN + qt * 64) * DH;
    unsigned qa[8][4];
#pragma unroll
    for (int k8 = 0; k8 < 8; k8++) {
        qa[k8][0] = __float_as_uint(Qg[r0 * 64 + k8 * 8 + l4]);
        qa[k8][1] = __float_as_uint(Qg[r1 * 64 + k8 * 8 + l4]);
        qa[k8][2] = __float_as_uint(Qg[r0 * 64 + k8 * 8 + l4 + 4]);
        qa[k8][3] = __float_as_uint(Qg[r1 * 64 + k8 * 8 + l4 + 4]);
    }

    float m_0 = -1e30f, m_1 = -1e30f, l_0 = 0.f, l_1 = 0.f;
    float o[8][4];
#pragma unroll
    for (int nt = 0; nt < 8; nt++)
#pragma unroll
        for (int e = 0; e < 4; e++) o[nt][e] = 0.f;

    const float* Kg = g_K + (size_t)bh * N3 * DH;
    const float* Vg = g_V + (size_t)bh * N3 * DH;

    for (int kt = 0; kt < 24; kt++) {
        __syncthreads();
#pragma unroll
        for (int v = 0; v < 8; v++) {
            int idx = tid + v * 128;
            int r = idx >> 4, c4 = (idx & 15) << 2;
            float4 kk = *(const float4*)(Kg + (size_t)(kt * 64 + r) * 64 + c4);
            *(uint4*)&Ks[r * SK + c4] =
                make_uint4(__float_as_uint(kk.x), __float_as_uint(kk.y),
                           __float_as_uint(kk.z), __float_as_uint(kk.w));
            float4 vv = *(const float4*)(Vg + (size_t)(kt * 64 + r) * 64 + c4);
            *(uint4*)&Vs[r * SV + c4] =
                make_uint4(__float_as_uint(vv.x), __float_as_uint(vv.y),
                           __float_as_uint(vv.z), __float_as_uint(vv.w));
        }
        __syncthreads();

        // S = Q K^T
        float s[8][4];
#pragma unroll
        for (int nt = 0; nt < 8; nt++)
#pragma unroll
            for (int e = 0; e < 4; e++) s[nt][e] = 0.f;
#pragma unroll
        for (int k8 = 0; k8 < 8; k8++) {
#pragma unroll
            for (int nt = 0; nt < 8; nt++) {
                unsigned bf[2];
                int key = nt * 8 + grp;
                bf[0] = Ks[key * SK + k8 * 8 + l4];
                bf[1] = Ks[key * SK + k8 * 8 + l4 + 4];
                mma8(s[nt], qa[k8], bf);
            }
        }

        // Masked-row substitution (whole q-row -> NEG)
        if (!on0) {
#pragma unroll
            for (int nt = 0; nt < 8; nt++) { s[nt][0] = NEGV; s[nt][1] = NEGV; }
        }
        if (!on1) {
#pragma unroll
            for (int nt = 0; nt < 8; nt++) { s[nt][2] = NEGV; s[nt][3] = NEGV; }
        }

        // Online softmax (quad-reduced per row)
        float mx0 = NEGV, mx1 = NEGV;
#pragma unroll
        for (int nt = 0; nt < 8; nt++) {
            mx0 = fmaxf(mx0, fmaxf(s[nt][0], s[nt][1]));
            mx1 = fmaxf(mx1, fmaxf(s[nt][2], s[nt][3]));
        }
        mx0 = fmaxf(mx0, __shfl_xor_sync(0xffffffffu, mx0, 1));
        mx0 = fmaxf(mx0, __shfl_xor_sync(0xffffffffu, mx0, 2));
        mx1 = fmaxf(mx1, __shfl_xor_sync(0xffffffffu, mx1, 1));
        mx1 = fmaxf(mx1, __shfl_xor_sync(0xffffffffu, mx1, 2));

        float mn0 = fmaxf(m_0, mx0), mn1 = fmaxf(m_1, mx1);
        float al0 = __expf(m_0 - mn0), al1 = __expf(m_1 - mn1);
        m_0 = mn0; m_1 = mn1;

        float sum0 = 0.f, sum1 = 0.f;
#pragma unroll
        for (int nt = 0; nt < 8; nt++) {
            s[nt][0] = __expf(s[nt][0] - mn0);
            s[nt][1] = __expf(s[nt][1] - mn0);
            s[nt][2] = __expf(s[nt][2] - mn1);
            s[nt][3] = __expf(s[nt][3] - mn1);
            sum0 += s[nt][0] + s[nt][1];
            sum1 += s[nt][2] + s[nt][3];
        }
        sum0 += __shfl_xor_sync(0xffffffffu, sum0, 1);
        sum0 += __shfl_xor_sync(0xffffffffu, sum0, 2);
        sum1 += __shfl_xor_sync(0xffffffffu, sum1, 1);
        sum1 += __shfl_xor_sync(0xffffffffu, sum1, 2);
        l_0 = l_0 * al0 + sum0;
        l_1 = l_1 * al1 + sum1;

#pragma unroll
        for (int nt = 0; nt < 8; nt++) {
            o[nt][0] *= al0; o[nt][1] *= al0;
            o[nt][2] *= al1; o[nt][3] *= al1;
        }

        // O += P @ V  (P C-frag -> A-frag via quad shuffles)
        const int src = (grp << 2) | (l4 >> 1);
        const bool odd = (l4 & 1);
#pragma unroll
        for (int k8 = 0; k8 < 8; k8++) {
            float t0 = __shfl_sync(0xffffffffu, s[k8][0], src);
            float t1 = __shfl_sync(0xffffffffu, s[k8][1], src);
            float t2 = __shfl_sync(0xffffffffu, s[k8][2], src);
            float t3 = __shfl_sync(0xffffffffu, s[k8][3], src);
            float u0 = __shfl_sync(0xffffffffu, s[k8][0], src + 2);
            float u1 = __shfl_sync(0xffffffffu, s[k8][1], src + 2);
            float u2 = __shfl_sync(0xffffffffu, s[k8][2], src + 2);
            float u3 = __shfl_sync(0xffffffffu, s[k8][3], src + 2);
            unsigned pa[4];
            pa[0] = f2t(odd ? t1 : t0);
            pa[1] = f2t(odd ? t3 : t2);
            pa[2] = f2t(odd ? u1 : u0);
            pa[3] = f2t(odd ? u3 : u2);
#pragma unroll
            for (int nt = 0; nt < 8; nt++) {
                unsigned bf[2];
                bf[0] = Vs[(k8 * 8 + l4) * SV + nt * 8 + grp];
                bf[1] = Vs[(k8 * 8 + l4 + 4) * SV + nt * 8 + grp];
                mma8(o[nt], pa, bf);
            }
        }
    }

    // Epilogue: normalize, write [mod][b][n][h*64+d]
    float linv0 = 1.f / l_0, linv1 = 1.f / l_1;
    size_t base0 = (((size_t)mod * BB + b) * NN + qt * 64 + r0) * DI + h * 64;
    size_t base1 = (((size_t)mod * BB + b) * NN + qt * 64 + r1) * DI + h * 64;
#pragma unroll
    for (int nt = 0; nt < 8; nt++) {
        int dd = nt * 8 + l4 * 2;
        *(float2*)(g_O + base0 + dd) = make_float2(o[nt][0] * linv0, o[nt][1] * linv0);
        *(float2*)(g_O + base1 + dd) = make_float2(o[nt][2] * linv1, o[nt][3] * linv1);
    }
}

// ---------------------------------------------------------------------------
// Input order: 0:x0 1:m0 2:Wqkv0 3:Wout0 | 4:x1 5:m1 6:Wqkv1 7:Wout1 | 8:...
// ---------------------------------------------------------------------------
extern "C" void kernel_launch(void* const* d_in, const int* in_sizes, int n_in,
                              void* d_out, int out_size) {
    const float* x0  = (const float*)d_in[0];
    const int*   m0  = (const int*)d_in[1];
    const float* wq0 = (const float*)d_in[2];
    const float* wo0 = (const float*)d_in[3];
    const float* x1  = (const float*)d_in[4];
    const int*   m1  = (const int*)d_in[5];
    const float* wq1 = (const float*)d_in[6];
    const float* wo1 = (const float*)d_in[7];
    const float* x2  = (const float*)d_in[8];
    const int*   m2  = (const int*)d_in[9];
    const float* wq2 = (const float*)d_in[10];
    const float* wo2 = (const float*)d_in[11];
    float* out = (float*)d_out;

    gemm_tc<1536, 0><<<dim3(12, 32, 3), 256>>>(x0, x1, x2, wq0, wq1, wq2, nullptr);
    attn_tc<<<dim3(8, 64, 3), 128>>>(m0, m1, m2);
    gemm_tc<512, 1><<<dim3(4, 32, 3), 256>>>(nullptr, nullptr, nullptr, wo0, wo1, wo2, out);
}

// round 4
// speedup vs baseline: 3.6843x; 1.0611x over previous
#include <cuda_runtime.h>
#include <math.h>

#define BB 8
#define NN 512
#define HH 8
#define DH 64
#define DI 512
#define N3 1536
#define SCALE 0.125f
#define NEGV -1e9f

// Scratch (device globals). All tf32-exact fp32 bits.
__device__ float g_X[3ull * 4096 * 512];          // pre-rounded inputs
__device__ float g_Wq[3ull * 512 * 1536];         // pre-rounded Wqkv
__device__ float g_Wo[3ull * 512 * 512];          // pre-rounded Wout
__device__ float g_Q[3ull * BB * HH * NN * DH];   // [mod][b][h][n][d], pre-scaled
__device__ float g_K[(size_t)BB * HH * N3 * DH];  // [b][h][3n][d]
__device__ float g_V[(size_t)BB * HH * N3 * DH];
__device__ float g_O[3ull * BB * NN * DI];        // [mod][b][n][h*d], pre-rounded

__device__ __forceinline__ unsigned f2t(float f) {
    unsigned u;
    asm("cvt.rna.tf32.f32 %0, %1;" : "=r"(u) : "f"(f));
    return u;
}
__device__ __forceinline__ float tf32r(float f) { return __uint_as_float(f2t(f)); }

__device__ __forceinline__ void mma8(float d[4], const unsigned a[4], const unsigned b[2]) {
    asm volatile(
        "mma.sync.aligned.m16n8k8.row.col.f32.tf32.tf32.f32 "
        "{%0,%1,%2,%3}, {%4,%5,%6,%7}, {%8,%9}, {%0,%1,%2,%3};"
        : "+f"(d[0]), "+f"(d[1]), "+f"(d[2]), "+f"(d[3])
        : "r"(a[0]), "r"(a[1]), "r"(a[2]), "r"(a[3]), "r"(b[0]), "r"(b[1]));
}

__device__ __forceinline__ void cpa16(unsigned* dst, const float* src) {
    unsigned d = (unsigned)__cvta_generic_to_shared(dst);
    asm volatile("cp.async.cg.shared.global [%0], [%1], 16;\n" ::"r"(d), "l"(src));
}
#define CP_COMMIT asm volatile("cp.async.commit_group;\n" ::)
#define CP_WAIT1 asm volatile("cp.async.wait_group 1;\n" ::)
#define CP_WAIT0 asm volatile("cp.async.wait_group 0;\n" ::)

// ---------------------------------------------------------------------------
// Prep: tf32-round inputs into device globals. grid (3072, 3), block 256.
// ---------------------------------------------------------------------------
__global__ void prep_round(const float* __restrict__ x0, const float* __restrict__ wq0,
                           const float* __restrict__ wo0, const float* __restrict__ x1,
                           const float* __restrict__ wq1, const float* __restrict__ wo1,
                           const float* __restrict__ x2, const float* __restrict__ wq2,
                           const float* __restrict__ wo2) {
    const int mod = blockIdx.y;
    const float* __restrict__ X = (mod == 0) ? x0 : (mod == 1) ? x1 : x2;
    const float* __restrict__ Wq = (mod == 0) ? wq0 : (mod == 1) ? wq1 : wq2;
    const float* __restrict__ Wo = (mod == 0) ? wo0 : (mod == 1) ? wo1 : wo2;
    int i = blockIdx.x * 256 + threadIdx.x;   // float4 index
    const float* src;
    float* dst;
    int off;
    if (i < 524288) {                 // X: 4096*512/4
        off = i;
        src = X;
        dst = g_X + (size_t)mod * 4096 * 512;
    } else if (i < 720896) {          // Wq: 512*1536/4
        off = i - 524288;
        src = Wq;
        dst = g_Wq + (size_t)mod * 512 * 1536;
    } else {                          // Wo: 512*512/4
        off = i - 720896;
        src = Wo;
        dst = g_Wo + (size_t)mod * 512 * 512;
    }
    float4 v = *(const float4*)(src + (size_t)off * 4);
    v.x = tf32r(v.x); v.y = tf32r(v.y); v.z = tf32r(v.z); v.w = tf32r(v.w);
    *(float4*)(dst + (size_t)off * 4) = v;
}

// ---------------------------------------------------------------------------
// Tensor-core GEMM: C[4096, NC] = X[4096,512] @ W[512,NC], inputs pre-rounded.
// 128x128 tile, 256 threads (8 warps 2x4), k-chunk 32, cp.async 2-stage.
// EPI=0: QKV scatter epilogue.  EPI=1: direct fp32 store to out.
// ---------------------------------------------------------------------------
#define SA 36
#define SB 132
#define XS_W (128 * SA)
#define WS_W (32 * SB)
#define GEMM_SMEM ((2 * XS_W + 2 * WS_W) * 4)

template <int NC, int EPI>
__global__ __launch_bounds__(256) void gemm_tc(const float* __restrict__ Xbase,
                                               const float* __restrict__ Wbase,
                                               float* __restrict__ out) {
    extern __shared__ unsigned sh[];
    unsigned* Xs = sh;                  // 2 stages
    unsigned* Ws = sh + 2 * XS_W;

    const int mod = blockIdx.z;
    const float* __restrict__ X = Xbase + (size_t)mod * 4096 * 512;
    const float* __restrict__ W = Wbase + (size_t)mod * 512 * NC;

    const int tid = threadIdx.x;
    const int wid = tid >> 5, lane = tid & 31;
    const int grp = lane >> 2, l4 = lane & 3;
    const int wm = wid >> 2, wn = wid & 3;
    const int rowbase = blockIdx.y * 128;
    const int colbase = blockIdx.x * 128;

    float c[4][4][4];
#pragma unroll
    for (int mt = 0; mt < 4; mt++)
#pragma unroll
        for (int nt = 0; nt < 4; nt++)
#pragma unroll
            for (int e = 0; e < 4; e++) c[mt][nt][e] = 0.f;

    const int xr = tid >> 3, xc = (tid & 7) << 2;      // +32 rows per i
    const int wr = tid >> 5, wc = (tid & 31) << 2;     // +8 rows per i

    auto ldg_async = [&](int stage, int k0) {
        unsigned* Xst = Xs + stage * XS_W;
        unsigned* Wst = Ws + stage * WS_W;
#pragma unroll
        for (int i = 0; i < 4; i++) {
            cpa16(&Xst[(xr + i * 32) * SA + xc],
                  X + (size_t)(rowbase + xr + i * 32) * 512 + k0 + xc);
            cpa16(&Wst[(wr + i * 8) * SB + wc],
                  W + (size_t)(k0 + wr + i * 8) * NC + colbase + wc);
        }
    };

    ldg_async(0, 0);
    CP_COMMIT;

    for (int chunk = 0; chunk < 16; chunk++) {
        if (chunk < 15) {
            ldg_async((chunk + 1) & 1, (chunk + 1) * 32);
            CP_COMMIT;
            CP_WAIT1;
        } else {
            CP_WAIT0;
        }
        __syncthreads();

        const unsigned* Xst = Xs + (chunk & 1) * XS_W;
        const unsigned* Wst = Ws + (chunk & 1) * WS_W;
#pragma unroll
        for (int k8 = 0; k8 < 4; k8++) {
            unsigned a[4][4];
#pragma unroll
            for (int mt = 0; mt < 4; mt++) {
                int r0 = wm * 64 + mt * 16 + grp;
                a[mt][0] = Xst[r0 * SA + k8 * 8 + l4];
                a[mt][1] = Xst[(r0 + 8) * SA + k8 * 8 + l4];
                a[mt][2] = Xst[r0 * SA + k8 * 8 + l4 + 4];
                a[mt][3] = Xst[(r0 + 8) * SA + k8 * 8 + l4 + 4];
            }
#pragma unroll
            for (int nt = 0; nt < 4; nt++) {
                unsigned b[2];
                int col = wn * 32 + nt * 8 + grp;
                b[0] = Wst[(k8 * 8 + l4) * SB + col];
                b[1] = Wst[(k8 * 8 + l4 + 4) * SB + col];
#pragma unroll
                for (int mt = 0; mt < 4; mt++) mma8(c[mt][nt], a[mt], b);
            }
        }
        __syncthreads();
    }

    // Epilogue
#pragma unroll
    for (int mt = 0; mt < 4; mt++) {
        int gr0 = rowbase + wm * 64 + mt * 16 + grp;
        int gr1 = gr0 + 8;
#pragma unroll
        for (int nt = 0; nt < 4; nt++) {
            int gc = colbase + wn * 32 + nt * 8 + l4 * 2;
            if (EPI == 1) {
                *(float2*)(out + ((size_t)mod * 4096 + gr0) * 512 + gc) =
                    make_float2(c[mt][nt][0], c[mt][nt][1]);
                *(float2*)(out + ((size_t)mod * 4096 + gr1) * 512 + gc) =
                    make_float2(c[mt][nt][2], c[mt][nt][3]);
            } else {
#pragma unroll
                for (int e = 0; e < 4; e++) {
                    int gr = (e < 2) ? gr0 : gr1;
                    int gcc = gc + (e & 1);
                    float v = c[mt][nt][e];
                    int b = gr >> 9, n = gr & 511;
                    if (gcc < 512) {
                        int h = gcc >> 6, dd = gcc & 63;
                        g_Q[((((size_t)mod * BB + b) * HH + h) * NN + n) * DH + dd] =
                            tf32r(v * SCALE);
                    } else if (gcc < 1024) {
                        int c2 = gcc - 512, h = c2 >> 6, dd = c2 & 63;
                        g_K[(((size_t)b * HH + h) * N3 + mod * NN + n) * DH + dd] = tf32r(v);
                    } else {
                        int c2 = gcc - 1024, h = c2 >> 6, dd = c2 & 63;
                        g_V[(((size_t)b * HH + h) * N3 + mod * NN + n) * DH + dd] = tf32r(v);
                    }
                }
            }
        }
    }
}

// ---------------------------------------------------------------------------
// Tensor-core flash attention. grid (4 qtiles of 128, 64 bh, 3 mod), 256 thr.
// Warp w handles q-rows [w*16, w*16+16) of the 128-row tile. K/V tiles shared
// by all 8 warps, cp.async double-buffered.
// ---------------------------------------------------------------------------
#define SK 68
#define SV 72
#define KS_W (64 * SK)
#define VS_W (64 * SV)
#define ATT_SMEM ((2 * KS_W + 2 * VS_W) * 4)

__global__ __launch_bounds__(256) void attn_tc(const int* __restrict__ m0,
                                               const int* __restrict__ m1,
                                               const int* __restrict__ m2) {
    extern __shared__ unsigned sh[];
    unsigned* Ks = sh;
    unsigned* Vs = sh + 2 * KS_W;

    const int mod = blockIdx.z;
    const int bh = blockIdx.y;
    const int b = bh >> 3, h = bh & 7;
    const int qt = blockIdx.x;                // 128-row q tile
    const int tid = threadIdx.x;
    const int wid = tid >> 5, lane = tid & 31;
    const int grp = lane >> 2, l4 = lane & 3;

    const int* __restrict__ M = (mod == 0) ? m0 : (mod == 1) ? m1 : m2;

    const int r0 = wid * 16 + grp;            // within 128-row q tile
    const int r1 = r0 + 8;
    const bool on0 = (M[b * NN + qt * 128 + r0] != 0);
    const bool on1 = (M[b * NN + qt * 128 + r1] != 0);

    // Q A-fragments (g_Q tf32-exact, pre-scaled)
    const float* Qg = g_Q + ((((size_t)mod * BB + b) * HH + h) * NN + qt * 128) * DH;
    unsigned qa[8][4];
#pragma unroll
    for (int k8 = 0; k8 < 8; k8++) {
        qa[k8][0] = __float_as_uint(Qg[r0 * 64 + k8 * 8 + l4]);
        qa[k8][1] = __float_as_uint(Qg[r1 * 64 + k8 * 8 + l4]);
        qa[k8][2] = __float_as_uint(Qg[r0 * 64 + k8 * 8 + l4 + 4]);
        qa[k8][3] = __float_as_uint(Qg[r1 * 64 + k8 * 8 + l4 + 4]);
    }

    float m_0 = -1e30f, m_1 = -1e30f, l_0 = 0.f, l_1 = 0.f;
    float o[8][4];
#pragma unroll
    for (int nt = 0; nt < 8; nt++)
#pragma unroll
        for (int e = 0; e < 4; e++) o[nt][e] = 0.f;

    const float* Kg = g_K + (size_t)bh * N3 * DH;
    const float* Vg = g_V + (size_t)bh * N3 * DH;

    const int kr = tid >> 2, kc = (tid & 3) << 4;     // 64 rows, 4 f4-chunks each... (row,col16)
    // 64 rows x 16 float4 per row = 1024 f4; thread covers 4: rows tid>>2 (+0),
    // cols (tid&3)*4 floats*4 = 16-float steps -> offsets kc + {0,16,32,48}? No:
    // use v = tid + i*256: r = v>>4, c = (v&15)*4.
    auto ldkv_async = [&](int stage, int kt) {
        unsigned* Kst = Ks + stage * KS_W;
        unsigned* Vst = Vs + stage * VS_W;
#pragma unroll
        for (int i = 0; i < 4; i++) {
            int v = tid + i * 256;
            int r = v >> 4, c4 = (v & 15) << 2;
            cpa16(&Kst[r * SK + c4], Kg + (size_t)(kt * 64 + r) * 64 + c4);
            cpa16(&Vst[r * SV + c4], Vg + (size_t)(kt * 64 + r) * 64 + c4);
        }
    };
    (void)kr; (void)kc;

    ldkv_async(0, 0);
    CP_COMMIT;

    for (int kt = 0; kt < 24; kt++) {
        if (kt < 23) {
            ldkv_async((kt + 1) & 1, kt + 1);
            CP_COMMIT;
            CP_WAIT1;
        } else {
            CP_WAIT0;
        }
        __syncthreads();

        const unsigned* Kst = Ks + (kt & 1) * KS_W;
        const unsigned* Vst = Vs + (kt & 1) * VS_W;

        // S = Q K^T
        float s[8][4];
#pragma unroll
        for (int nt = 0; nt < 8; nt++)
#pragma unroll
            for (int e = 0; e < 4; e++) s[nt][e] = 0.f;
#pragma unroll
        for (int k8 = 0; k8 < 8; k8++) {
#pragma unroll
            for (int nt = 0; nt < 8; nt++) {
                unsigned bf[2];
                int key = nt * 8 + grp;
                bf[0] = Kst[key * SK + k8 * 8 + l4];
                bf[1] = Kst[key * SK + k8 * 8 + l4 + 4];
                mma8(s[nt], qa[k8], bf);
            }
        }

        // Masked-row substitution
        if (!on0) {
#pragma unroll
            for (int nt = 0; nt < 8; nt++) { s[nt][0] = NEGV; s[nt][1] = NEGV; }
        }
        if (!on1) {
#pragma unroll
            for (int nt = 0; nt < 8; nt++) { s[nt][2] = NEGV; s[nt][3] = NEGV; }
        }

        // Online softmax
        float mx0 = NEGV, mx1 = NEGV;
#pragma unroll
        for (int nt = 0; nt < 8; nt++) {
            mx0 = fmaxf(mx0, fmaxf(s[nt][0], s[nt][1]));
            mx1 = fmaxf(mx1, fmaxf(s[nt][2], s[nt][3]));
        }
        mx0 = fmaxf(mx0, __shfl_xor_sync(0xffffffffu, mx0, 1));
        mx0 = fmaxf(mx0, __shfl_xor_sync(0xffffffffu, mx0, 2));
        mx1 = fmaxf(mx1, __shfl_xor_sync(0xffffffffu, mx1, 1));
        mx1 = fmaxf(mx1, __shfl_xor_sync(0xffffffffu, mx1, 2));

        float mn0 = fmaxf(m_0, mx0), mn1 = fmaxf(m_1, mx1);
        float al0 = __expf(m_0 - mn0), al1 = __expf(m_1 - mn1);
        m_0 = mn0; m_1 = mn1;

        float sum0 = 0.f, sum1 = 0.f;
#pragma unroll
        for (int nt = 0; nt < 8; nt++) {
            s[nt][0] = __expf(s[nt][0] - mn0);
            s[nt][1] = __expf(s[nt][1] - mn0);
            s[nt][2] = __expf(s[nt][2] - mn1);
            s[nt][3] = __expf(s[nt][3] - mn1);
            sum0 += s[nt][0] + s[nt][1];
            sum1 += s[nt][2] + s[nt][3];
        }
        sum0 += __shfl_xor_sync(0xffffffffu, sum0, 1);
        sum0 += __shfl_xor_sync(0xffffffffu, sum0, 2);
        sum1 += __shfl_xor_sync(0xffffffffu, sum1, 1);
        sum1 += __shfl_xor_sync(0xffffffffu, sum1, 2);
        l_0 = l_0 * al0 + sum0;
        l_1 = l_1 * al1 + sum1;

#pragma unroll
        for (int nt = 0; nt < 8; nt++) {
            o[nt][0] *= al0; o[nt][1] *= al0;
            o[nt][2] *= al1; o[nt][3] *= al1;
        }

        // O += P @ V  (C-frag -> A-frag via quad shuffles)
        const int src = (grp << 2) | (l4 >> 1);
        const bool odd = (l4 & 1);
#pragma unroll
        for (int k8 = 0; k8 < 8; k8++) {
            float t0 = __shfl_sync(0xffffffffu, s[k8][0], src);
            float t1 = __shfl_sync(0xffffffffu, s[k8][1], src);
            float t2 = __shfl_sync(0xffffffffu, s[k8][2], src);
            float t3 = __shfl_sync(0xffffffffu, s[k8][3], src);
            float u0 = __shfl_sync(0xffffffffu, s[k8][0], src + 2);
            float u1 = __shfl_sync(0xffffffffu, s[k8][1], src + 2);
            float u2 = __shfl_sync(0xffffffffu, s[k8][2], src + 2);
            float u3 = __shfl_sync(0xffffffffu, s[k8][3], src + 2);
            unsigned pa[4];
            pa[0] = f2t(odd ? t1 : t0);
            pa[1] = f2t(odd ? t3 : t2);
            pa[2] = f2t(odd ? u1 : u0);
            pa[3] = f2t(odd ? u3 : u2);
#pragma unroll
            for (int nt = 0; nt < 8; nt++) {
                unsigned bf[2];
                bf[0] = Vst[(k8 * 8 + l4) * SV + nt * 8 + grp];
                bf[1] = Vst[(k8 * 8 + l4 + 4) * SV + nt * 8 + grp];
                mma8(o[nt], pa, bf);
            }
        }
        __syncthreads();
    }

    // Epilogue: normalize, tf32-round (feeds out GEMM), write [mod][b][n][h*64+d]
    float linv0 = 1.f / l_0, linv1 = 1.f / l_1;
    size_t base0 = (((size_t)mod * BB + b) * NN + qt * 128 + r0) * DI + h * 64;
    size_t base1 = (((size_t)mod * BB + b) * NN + qt * 128 + r1) * DI + h * 64;
#pragma unroll
    for (int nt = 0; nt < 8; nt++) {
        int dd = nt * 8 + l4 * 2;
        *(float2*)(g_O + base0 + dd) =
            make_float2(tf32r(o[nt][0] * linv0), tf32r(o[nt][1] * linv0));
        *(float2*)(g_O + base1 + dd) =
            make_float2(tf32r(o[nt][2] * linv1), tf32r(o[nt][3] * linv1));
    }
}

// ---------------------------------------------------------------------------
// Input order: 0:x0 1:m0 2:Wqkv0 3:Wout0 | 4:x1 5:m1 6:Wqkv1 7:Wout1 | 8:...
// ---------------------------------------------------------------------------
extern "C" void kernel_launch(void* const* d_in, const int* in_sizes, int n_in,
                              void* d_out, int out_size) {
    const float* x0  = (const float*)d_in[0];
    const int*   m0  = (const int*)d_in[1];
    const float* wq0 = (const float*)d_in[2];
    const float* wo0 = (const float*)d_in[3];
    const float* x1  = (const float*)d_in[4];
    const int*   m1  = (const int*)d_in[5];
    const float* wq1 = (const float*)d_in[6];
    const float* wo1 = (const float*)d_in[7];
    const float* x2  = (const float*)d_in[8];
    const int*   m2  = (const int*)d_in[9];
    const float* wq2 = (const float*)d_in[10];
    const float* wo2 = (const float*)d_in[11];
    float* out = (float*)d_out;

    static int configured = 0;
    if (!configured) {
        cudaFuncSetAttribute(gemm_tc<1536, 0>,
                             cudaFuncAttributeMaxDynamicSharedMemorySize, GEMM_SMEM);
        cudaFuncSetAttribute(gemm_tc<512, 1>,
                             cudaFuncAttributeMaxDynamicSharedMemorySize, GEMM_SMEM);
        cudaFuncSetAttribute(attn_tc,
                             cudaFuncAttributeMaxDynamicSharedMemorySize, ATT_SMEM);
        configured = 1;
    }

    float *gx, *gwq, *gwo;
    cudaGetSymbolAddress((void**)&gx, g_X);
    cudaGetSymbolAddress((void**)&gwq, g_Wq);
    cudaGetSymbolAddress((void**)&gwo, g_Wo);
    float* go;
    cudaGetSymbolAddress((void**)&go, g_O);

    prep_round<<<dim3(3072, 3), 256>>>(x0, wq0, wo0, x1, wq1, wo1, x2, wq2, wo2);
    gemm_tc<1536, 0><<<dim3(12, 32, 3), 256, GEMM_SMEM>>>(gx, gwq, nullptr);
    attn_tc<<<dim3(4, 64, 3), 256, ATT_SMEM>>>(m0, m1, m2);
    gemm_tc<512, 1><<<dim3(4, 32, 3), 256, GEMM_SMEM>>>(go, gwo, out);
}

// round 5
// speedup vs baseline: 3.8978x; 1.0579x over previous
#include <cuda_runtime.h>
#include <math.h>

#define BB 8
#define NN 512
#define HH 8
#define DH 64
#define DI 512
#define N3 1536
#define SCALE 0.125f
#define NEGV -1e9f

// Scratch (device globals). All tf32-exact fp32 bits.
__device__ float g_X[3ull * 4096 * 512];          // pre-rounded inputs
__device__ float g_Wq[3ull * 512 * 1536];         // pre-rounded Wqkv
__device__ float g_Wo[3ull * 512 * 512];          // pre-rounded Wout
__device__ float g_Q[3ull * BB * HH * NN * DH];   // [mod][b][h][n][d], pre-scaled
__device__ float g_K[(size_t)BB * HH * N3 * DH];  // [b][h][3n][d]
__device__ float g_V[(size_t)BB * HH * N3 * DH];
__device__ float g_O[3ull * BB * NN * DI];        // [mod][b][n][h*d], pre-rounded

__device__ __forceinline__ unsigned f2t(float f) {
    unsigned u;
    asm("cvt.rna.tf32.f32 %0, %1;" : "=r"(u) : "f"(f));
    return u;
}
__device__ __forceinline__ float tf32r(float f) { return __uint_as_float(f2t(f)); }

__device__ __forceinline__ void mma8(float d[4], const unsigned a[4], const unsigned b[2]) {
    asm volatile(
        "mma.sync.aligned.m16n8k8.row.col.f32.tf32.tf32.f32 "
        "{%0,%1,%2,%3}, {%4,%5,%6,%7}, {%8,%9}, {%0,%1,%2,%3};"
        : "+f"(d[0]), "+f"(d[1]), "+f"(d[2]), "+f"(d[3])
        : "r"(a[0]), "r"(a[1]), "r"(a[2]), "r"(a[3]), "r"(b[0]), "r"(b[1]));
}

__device__ __forceinline__ void cpa16(unsigned* dst, const float* src) {
    unsigned d = (unsigned)__cvta_generic_to_shared(dst);
    asm volatile("cp.async.cg.shared.global [%0], [%1], 16;\n" ::"r"(d), "l"(src));
}
#define CP_COMMIT asm volatile("cp.async.commit_group;\n" ::)
#define CP_WAIT1 asm volatile("cp.async.wait_group 1;\n" ::)
#define CP_WAIT0 asm volatile("cp.async.wait_group 0;\n" ::)

// ---------------------------------------------------------------------------
// Prep: tf32-round inputs into device globals. grid (3072, 3), block 256.
// ---------------------------------------------------------------------------
__global__ void prep_round(const float* __restrict__ x0, const float* __restrict__ wq0,
                           const float* __restrict__ wo0, const float* __restrict__ x1,
                           const float* __restrict__ wq1, const float* __restrict__ wo1,
                           const float* __restrict__ x2, const float* __restrict__ wq2,
                           const float* __restrict__ wo2) {
    const int mod = blockIdx.y;
    const float* __restrict__ X = (mod == 0) ? x0 : (mod == 1) ? x1 : x2;
    const float* __restrict__ Wq = (mod == 0) ? wq0 : (mod == 1) ? wq1 : wq2;
    const float* __restrict__ Wo = (mod == 0) ? wo0 : (mod == 1) ? wo1 : wo2;
    int i = blockIdx.x * 256 + threadIdx.x;   // float4 index
    const float* src;
    float* dst;
    int off;
    if (i < 524288) {                 // X: 4096*512/4
        off = i;
        src = X;
        dst = g_X + (size_t)mod * 4096 * 512;
    } else if (i < 720896) {          // Wq: 512*1536/4
        off = i - 524288;
        src = Wq;
        dst = g_Wq + (size_t)mod * 512 * 1536;
    } else {                          // Wo: 512*512/4
        off = i - 720896;
        src = Wo;
        dst = g_Wo + (size_t)mod * 512 * 512;
    }
    float4 v = *(const float4*)(src + (size_t)off * 4);
    v.x = tf32r(v.x); v.y = tf32r(v.y); v.z = tf32r(v.z); v.w = tf32r(v.w);
    *(float4*)(dst + (size_t)off * 4) = v;
}

// ---------------------------------------------------------------------------
// Tensor-core GEMM: C[4096, NC] = X[4096,512] @ W[512,NC], inputs pre-rounded.
// Tile (MT*32)x128, 256 threads (8 warps, 2 x 4), warp tile (MT*16)x32.
// k-chunk 32, cp.async 2-stage. EPI=0: QKV scatter. EPI=1: direct store.
// ---------------------------------------------------------------------------
#define SA 36
#define SB 132
#define WS_W (32 * SB)

template <int NC, int EPI, int MT>
__global__ __launch_bounds__(256) void gemm_tc(const float* __restrict__ Xbase,
                                               const float* __restrict__ Wbase,
                                               float* __restrict__ out) {
    constexpr int ROWS = MT * 32;
    constexpr int XS_W = ROWS * SA;
    extern __shared__ unsigned sh[];
    unsigned* Xs = sh;                  // 2 stages
    unsigned* Ws = sh + 2 * XS_W;

    const int mod = blockIdx.z;
    const float* __restrict__ X = Xbase + (size_t)mod * 4096 * 512;
    const float* __restrict__ W = Wbase + (size_t)mod * 512 * NC;

    const int tid = threadIdx.x;
    const int wid = tid >> 5, lane = tid & 31;
    const int grp = lane >> 2, l4 = lane & 3;
    const int wm = wid >> 2, wn = wid & 3;
    const int rowbase = blockIdx.y * ROWS;
    const int colbase = blockIdx.x * 128;

    float c[MT][4][4];
#pragma unroll
    for (int mt = 0; mt < MT; mt++)
#pragma unroll
        for (int nt = 0; nt < 4; nt++)
#pragma unroll
            for (int e = 0; e < 4; e++) c[mt][nt][e] = 0.f;

    const int xr = tid >> 3, xc = (tid & 7) << 2;      // +32 rows per i
    const int wr = tid >> 5, wc = (tid & 31) << 2;     // +8 rows per i

    auto ldg_async = [&](int stage, int k0) {
        unsigned* Xst = Xs + stage * XS_W;
        unsigned* Wst = Ws + stage * WS_W;
#pragma unroll
        for (int i = 0; i < MT; i++)
            cpa16(&Xst[(xr + i * 32) * SA + xc],
                  X + (size_t)(rowbase + xr + i * 32) * 512 + k0 + xc);
#pragma unroll
        for (int i = 0; i < 4; i++)
            cpa16(&Wst[(wr + i * 8) * SB + wc],
                  W + (size_t)(k0 + wr + i * 8) * NC + colbase + wc);
    };

    ldg_async(0, 0);
    CP_COMMIT;

    for (int chunk = 0; chunk < 16; chunk++) {
        if (chunk < 15) {
            ldg_async((chunk + 1) & 1, (chunk + 1) * 32);
            CP_COMMIT;
            CP_WAIT1;
        } else {
            CP_WAIT0;
        }
        __syncthreads();

        const unsigned* Xst = Xs + (chunk & 1) * XS_W;
        const unsigned* Wst = Ws + (chunk & 1) * WS_W;
#pragma unroll
        for (int k8 = 0; k8 < 4; k8++) {
            unsigned a[MT][4];
#pragma unroll
            for (int mt = 0; mt < MT; mt++) {
                int r0 = wm * (MT * 16) + mt * 16 + grp;
                a[mt][0] = Xst[r0 * SA + k8 * 8 + l4];
                a[mt][1] = Xst[(r0 + 8) * SA + k8 * 8 + l4];
                a[mt][2] = Xst[r0 * SA + k8 * 8 + l4 + 4];
                a[mt][3] = Xst[(r0 + 8) * SA + k8 * 8 + l4 + 4];
            }
#pragma unroll
            for (int nt = 0; nt < 4; nt++) {
                unsigned b[2];
                int col = wn * 32 + nt * 8 + grp;
                b[0] = Wst[(k8 * 8 + l4) * SB + col];
                b[1] = Wst[(k8 * 8 + l4 + 4) * SB + col];
#pragma unroll
                for (int mt = 0; mt < MT; mt++) mma8(c[mt][nt], a[mt], b);
            }
        }
        __syncthreads();
    }

    // Epilogue
#pragma unroll
    for (int mt = 0; mt < MT; mt++) {
        int gr0 = rowbase + wm * (MT * 16) + mt * 16 + grp;
        int gr1 = gr0 + 8;
#pragma unroll
        for (int nt = 0; nt < 4; nt++) {
            int gc = colbase + wn * 32 + nt * 8 + l4 * 2;
            if (EPI == 1) {
                *(float2*)(out + ((size_t)mod * 4096 + gr0) * 512 + gc) =
                    make_float2(c[mt][nt][0], c[mt][nt][1]);
                *(float2*)(out + ((size_t)mod * 4096 + gr1) * 512 + gc) =
                    make_float2(c[mt][nt][2], c[mt][nt][3]);
            } else {
#pragma unroll
                for (int e = 0; e < 4; e++) {
                    int gr = (e < 2) ? gr0 : gr1;
                    int gcc = gc + (e & 1);
                    float v = c[mt][nt][e];
                    int b = gr >> 9, n = gr & 511;
                    if (gcc < 512) {
                        int h = gcc >> 6, dd = gcc & 63;
                        g_Q[((((size_t)mod * BB + b) * HH + h) * NN + n) * DH + dd] =
                            tf32r(v * SCALE);
                    } else if (gcc < 1024) {
                        int c2 = gcc - 512, h = c2 >> 6, dd = c2 & 63;
                        g_K[(((size_t)b * HH + h) * N3 + mod * NN + n) * DH + dd] = tf32r(v);
                    } else {
                        int c2 = gcc - 1024, h = c2 >> 6, dd = c2 & 63;
                        g_V[(((size_t)b * HH + h) * N3 + mod * NN + n) * DH + dd] = tf32r(v);
                    }
                }
            }
        }
    }
}

// ---------------------------------------------------------------------------
// Tensor-core flash attention. grid (8 qtiles of 64, 64 bh, 3 mod), 128 thr.
// Warp w handles q-rows [w*16, w*16+16). K/V cp.async double-buffered.
// 128-thread CTAs keep regs/CTA low -> 3 CTAs/SM (smem 71.7KB*3 fits 228KB).
// ---------------------------------------------------------------------------
#define SK 68
#define SV 72
#define KS_W (64 * SK)
#define VS_W (64 * SV)
#define ATT_SMEM ((2 * KS_W + 2 * VS_W) * 4)

__global__ __launch_bounds__(128, 3) void attn_tc(const int* __restrict__ m0,
                                                  const int* __restrict__ m1,
                                                  const int* __restrict__ m2) {
    extern __shared__ unsigned sh[];
    unsigned* Ks = sh;
    unsigned* Vs = sh + 2 * KS_W;

    const int mod = blockIdx.z;
    const int bh = blockIdx.y;
    const int b = bh >> 3, h = bh & 7;
    const int qt = blockIdx.x;                // 64-row q tile
    const int tid = threadIdx.x;
    const int wid = tid >> 5, lane = tid & 31;
    const int grp = lane >> 2, l4 = lane & 3;

    const int* __restrict__ M = (mod == 0) ? m0 : (mod == 1) ? m1 : m2;

    const int r0 = wid * 16 + grp;            // within 64-row q tile
    const int r1 = r0 + 8;
    const bool on0 = (M[b * NN + qt * 64 + r0] != 0);
    const bool on1 = (M[b * NN + qt * 64 + r1] != 0);

    // Q A-fragments (g_Q tf32-exact, pre-scaled)
    const float* Qg = g_Q + ((((size_t)mod * BB + b) * HH + h) * NN + qt * 64) * DH;
    unsigned qa[8][4];
#pragma unroll
    for (int k8 = 0; k8 < 8; k8++) {
        qa[k8][0] = __float_as_uint(Qg[r0 * 64 + k8 * 8 + l4]);
        qa[k8][1] = __float_as_uint(Qg[r1 * 64 + k8 * 8 + l4]);
        qa[k8][2] = __float_as_uint(Qg[r0 * 64 + k8 * 8 + l4 + 4]);
        qa[k8][3] = __float_as_uint(Qg[r1 * 64 + k8 * 8 + l4 + 4]);
    }

    float m_0 = -1e30f, m_1 = -1e30f, l_0 = 0.f, l_1 = 0.f;
    float o[8][4];
#pragma unroll
    for (int nt = 0; nt < 8; nt++)
#pragma unroll
        for (int e = 0; e < 4; e++) o[nt][e] = 0.f;

    const float* Kg = g_K + (size_t)bh * N3 * DH;
    const float* Vg = g_V + (size_t)bh * N3 * DH;

    auto ldkv_async = [&](int stage, int kt) {
        unsigned* Kst = Ks + stage * KS_W;
        unsigned* Vst = Vs + stage * VS_W;
#pragma unroll
        for (int i = 0; i < 8; i++) {
            int v = tid + i * 128;
            int r = v >> 4, c4 = (v & 15) << 2;
            cpa16(&Kst[r * SK + c4], Kg + (size_t)(kt * 64 + r) * 64 + c4);
            cpa16(&Vst[r * SV + c4], Vg + (size_t)(kt * 64 + r) * 64 + c4);
        }
    };

    ldkv_async(0, 0);
    CP_COMMIT;

    for (int kt = 0; kt < 24; kt++) {
        if (kt < 23) {
            ldkv_async((kt + 1) & 1, kt + 1);
            CP_COMMIT;
            CP_WAIT1;
        } else {
            CP_WAIT0;
        }
        __syncthreads();

        const unsigned* Kst = Ks + (kt & 1) * KS_W;
        const unsigned* Vst = Vs + (kt & 1) * VS_W;

        // S = Q K^T
        float s[8][4];
#pragma unroll
        for (int nt = 0; nt < 8; nt++)
#pragma unroll
            for (int e = 0; e < 4; e++) s[nt][e] = 0.f;
#pragma unroll
        for (int k8 = 0; k8 < 8; k8++) {
#pragma unroll
            for (int nt = 0; nt < 8; nt++) {
                unsigned bf[2];
                int key = nt * 8 + grp;
                bf[0] = Kst[key * SK + k8 * 8 + l4];
                bf[1] = Kst[key * SK + k8 * 8 + l4 + 4];
                mma8(s[nt], qa[k8], bf);
            }
        }

        // Masked-row substitution
        if (!on0) {
#pragma unroll
            for (int nt = 0; nt < 8; nt++) { s[nt][0] = NEGV; s[nt][1] = NEGV; }
        }
        if (!on1) {
#pragma unroll
            for (int nt = 0; nt < 8; nt++) { s[nt][2] = NEGV; s[nt][3] = NEGV; }
        }

        // Online softmax
        float mx0 = NEGV, mx1 = NEGV;
#pragma unroll
        for (int nt = 0; nt < 8; nt++) {
            mx0 = fmaxf(mx0, fmaxf(s[nt][0], s[nt][1]));
            mx1 = fmaxf(mx1, fmaxf(s[nt][2], s[nt][3]));
        }
        mx0 = fmaxf(mx0, __shfl_xor_sync(0xffffffffu, mx0, 1));
        mx0 = fmaxf(mx0, __shfl_xor_sync(0xffffffffu, mx0, 2));
        mx1 = fmaxf(mx1, __shfl_xor_sync(0xffffffffu, mx1, 1));
        mx1 = fmaxf(mx1, __shfl_xor_sync(0xffffffffu, mx1, 2));

        float mn0 = fmaxf(m_0, mx0), mn1 = fmaxf(m_1, mx1);
        float al0 = __expf(m_0 - mn0), al1 = __expf(m_1 - mn1);
        m_0 = mn0; m_1 = mn1;

        float sum0 = 0.f, sum1 = 0.f;
#pragma unroll
        for (int nt = 0; nt < 8; nt++) {
            s[nt][0] = __expf(s[nt][0] - mn0);
            s[nt][1] = __expf(s[nt][1] - mn0);
            s[nt][2] = __expf(s[nt][2] - mn1);
            s[nt][3] = __expf(s[nt][3] - mn1);
            sum0 += s[nt][0] + s[nt][1];
            sum1 += s[nt][2] + s[nt][3];
        }
        sum0 += __shfl_xor_sync(0xffffffffu, sum0, 1);
        sum0 += __shfl_xor_sync(0xffffffffu, sum0, 2);
        sum1 += __shfl_xor_sync(0xffffffffu, sum1, 1);
        sum1 += __shfl_xor_sync(0xffffffffu, sum1, 2);
        l_0 = l_0 * al0 + sum0;
        l_1 = l_1 * al1 + sum1;

#pragma unroll
        for (int nt = 0; nt < 8; nt++) {
            o[nt][0] *= al0; o[nt][1] *= al0;
            o[nt][2] *= al1; o[nt][3] *= al1;
        }

        // O += P @ V  (C-frag -> A-frag via quad shuffles)
        const int src = (grp << 2) | (l4 >> 1);
        const bool odd = (l4 & 1);
#pragma unroll
        for (int k8 = 0; k8 < 8; k8++) {
            float t0 = __shfl_sync(0xffffffffu, s[k8][0], src);
            float t1 = __shfl_sync(0xffffffffu, s[k8][1], src);
            float t2 = __shfl_sync(0xffffffffu, s[k8][2], src);
            float t3 = __shfl_sync(0xffffffffu, s[k8][3], src);
            float u0 = __shfl_sync(0xffffffffu, s[k8][0], src + 2);
            float u1 = __shfl_sync(0xffffffffu, s[k8][1], src + 2);
            float u2 = __shfl_sync(0xffffffffu, s[k8][2], src + 2);
            float u3 = __shfl_sync(0xffffffffu, s[k8][3], src + 2);
            unsigned pa[4];
            pa[0] = f2t(odd ? t1 : t0);
            pa[1] = f2t(odd ? t3 : t2);
            pa[2] = f2t(odd ? u1 : u0);
            pa[3] = f2t(odd ? u3 : u2);
#pragma unroll
            for (int nt = 0; nt < 8; nt++) {
                unsigned bf[2];
                bf[0] = Vst[(k8 * 8 + l4) * SV + nt * 8 + grp];
                bf[1] = Vst[(k8 * 8 + l4 + 4) * SV + nt * 8 + grp];
                mma8(o[nt], pa, bf);
            }
        }
        __syncthreads();
    }

    // Epilogue: normalize, tf32-round (feeds out GEMM), write [mod][b][n][h*64+d]
    float linv0 = 1.f / l_0, linv1 = 1.f / l_1;
    size_t base0 = (((size_t)mod * BB + b) * NN + qt * 64 + r0) * DI + h * 64;
    size_t base1 = (((size_t)mod * BB + b) * NN + qt * 64 + r1) * DI + h * 64;
#pragma unroll
    for (int nt = 0; nt < 8; nt++) {
        int dd = nt * 8 + l4 * 2;
        *(float2*)(g_O + base0 + dd) =
            make_float2(tf32r(o[nt][0] * linv0), tf32r(o[nt][1] * linv0));
        *(float2*)(g_O + base1 + dd) =
            make_float2(tf32r(o[nt][2] * linv1), tf32r(o[nt][3] * linv1));
    }
}

// ---------------------------------------------------------------------------
// Input order: 0:x0 1:m0 2:Wqkv0 3:Wout0 | 4:x1 5:m1 6:Wqkv1 7:Wout1 | 8:...
// ---------------------------------------------------------------------------
#define GEMM_SMEM_4 ((2 * 128 * SA + 2 * WS_W) * 4)
#define GEMM_SMEM_2 ((2 * 64 * SA + 2 * WS_W) * 4)

extern "C" void kernel_launch(void* const* d_in, const int* in_sizes, int n_in,
                              void* d_out, int out_size) {
    const float* x0  = (const float*)d_in[0];
    const int*   m0  = (const int*)d_in[1];
    const float* wq0 = (const float*)d_in[2];
    const float* wo0 = (const float*)d_in[3];
    const float* x1  = (const float*)d_in[4];
    const int*   m1  = (const int*)d_in[5];
    const float* wq1 = (const float*)d_in[6];
    const float* wo1 = (const float*)d_in[7];
    const float* x2  = (const float*)d_in[8];
    const int*   m2  = (const int*)d_in[9];
    const float* wq2 = (const float*)d_in[10];
    const float* wo2 = (const float*)d_in[11];
    float* out = (float*)d_out;

    static int configured = 0;
    if (!configured) {
        cudaFuncSetAttribute(gemm_tc<1536, 0, 4>,
                             cudaFuncAttributeMaxDynamicSharedMemorySize, GEMM_SMEM_4);
        cudaFuncSetAttribute(gemm_tc<512, 1, 2>,
                             cudaFuncAttributeMaxDynamicSharedMemorySize, GEMM_SMEM_2);
        cudaFuncSetAttribute(attn_tc,
                             cudaFuncAttributeMaxDynamicSharedMemorySize, ATT_SMEM);
        configured = 1;
    }

    float *gx, *gwq, *gwo, *go;
    cudaGetSymbolAddress((void**)&gx, g_X);
    cudaGetSymbolAddress((void**)&gwq, g_Wq);
    cudaGetSymbolAddress((void**)&gwo, g_Wo);
    cudaGetSymbolAddress((void**)&go, g_O);

    prep_round<<<dim3(3072, 3), 256>>>(x0, wq0, wo0, x1, wq1, wo1, x2, wq2, wo2);
    gemm_tc<1536, 0, 4><<<dim3(12, 32, 3), 256, GEMM_SMEM_4>>>(gx, gwq, nullptr);
    attn_tc<<<dim3(8, 64, 3), 128, ATT_SMEM>>>(m0, m1, m2);
    gemm_tc<512, 1, 2><<<dim3(4, 64, 3), 256, GEMM_SMEM_2>>>(go, gwo, out);
}

// round 6
// speedup vs baseline: 4.0186x; 1.0310x over previous
#include <cuda_runtime.h>
#include <math.h>

#define BB 8
#define NN 512
#define HH 8
#define DH 64
#define DI 512
#define N3 1536
#define SCALE 0.125f
#define NEGV -1e9f

// Scratch (device globals). All tf32-exact fp32 bits.
// k-dims stored with in-block perm8 so mma fragment pairs (k, k+4) are adjacent.
__device__ float g_X[3ull * 4096 * 512];          // [mod][row][perm k]
__device__ float g_Wq[3ull * 512 * 1536];         // [mod][k][n] (unpermuted)
__device__ float g_Wo[3ull * 512 * 512];          // [mod][k][n] (unpermuted)
__device__ float g_Q[3ull * BB * HH * NN * DH];   // [mod][b][h][n][perm d], pre-scaled
__device__ float g_K[(size_t)BB * HH * N3 * DH];  // [bh][key][perm d]
__device__ float g_VT[(size_t)BB * HH * DH * N3]; // [bh][d][perm key]  (transposed!)
__device__ float g_O[3ull * BB * NN * DI];        // [mod][b][n][perm (h*64+d)]

__device__ __forceinline__ int perm8(int j) { return ((j & 3) << 1) | (j >> 2); }

__device__ __forceinline__ unsigned f2t(float f) {
    unsigned u;
    asm("cvt.rna.tf32.f32 %0, %1;" : "=r"(u) : "f"(f));
    return u;
}
__device__ __forceinline__ float tf32r(float f) { return __uint_as_float(f2t(f)); }

__device__ __forceinline__ void mma8(float d[4], const unsigned a[4], const unsigned b[2]) {
    asm volatile(
        "mma.sync.aligned.m16n8k8.row.col.f32.tf32.tf32.f32 "
        "{%0,%1,%2,%3}, {%4,%5,%6,%7}, {%8,%9}, {%0,%1,%2,%3};"
        : "+f"(d[0]), "+f"(d[1]), "+f"(d[2]), "+f"(d[3])
        : "r"(a[0]), "r"(a[1]), "r"(a[2]), "r"(a[3]), "r"(b[0]), "r"(b[1]));
}

__device__ __forceinline__ void cpa16(unsigned* dst, const float* src) {
    unsigned d = (unsigned)__cvta_generic_to_shared(dst);
    asm volatile("cp.async.cg.shared.global [%0], [%1], 16;\n" ::"r"(d), "l"(src));
}
#define CP_COMMIT asm volatile("cp.async.commit_group;\n" ::)
#define CP_WAIT1 asm volatile("cp.async.wait_group 1;\n" ::)
#define CP_WAIT0 asm volatile("cp.async.wait_group 0;\n" ::)

// ---------------------------------------------------------------------------
// Prep: tf32-round inputs; X additionally column-permuted. grid (3072,3), 256.
// ---------------------------------------------------------------------------
__global__ void prep_round(const float* __restrict__ x0, const float* __restrict__ wq0,
                           const float* __restrict__ wo0, const float* __restrict__ x1,
                           const float* __restrict__ wq1, const float* __restrict__ wo1,
                           const float* __restrict__ x2, const float* __restrict__ wq2,
                           const float* __restrict__ wo2) {
    const int mod = blockIdx.y;
    const float* __restrict__ X = (mod == 0) ? x0 : (mod == 1) ? x1 : x2;
    const float* __restrict__ Wq = (mod == 0) ? wq0 : (mod == 1) ? wq1 : wq2;
    const float* __restrict__ Wo = (mod == 0) ? wo0 : (mod == 1) ? wo1 : wo2;
    int i = blockIdx.x * 256 + threadIdx.x;   // float4 index
    if (i < 524288) {                          // X: permuted gather
        int o = i * 4;
        int row = o >> 9, c = o & 511;
        int base = c & ~7;
        float v[4];
#pragma unroll
        for (int q = 0; q < 4; q++) {
            int qq = (c + q) & 7;
            int j = ((qq & 1) << 2) | (qq >> 1);     // inverse perm
            v[q] = tf32r(X[(size_t)row * 512 + base + j]);
        }
        *(float4*)(g_X + (size_t)mod * 4096 * 512 + o) =
            make_float4(v[0], v[1], v[2], v[3]);
    } else {
        const float* src;
        float* dst;
        int off;
        if (i < 720896) { off = i - 524288; src = Wq; dst = g_Wq + (size_t)mod * 512 * 1536; }
        else            { off = i - 720896; src = Wo; dst = g_Wo + (size_t)mod * 512 * 512; }
        float4 v = *(const float4*)(src + (size_t)off * 4);
        v.x = tf32r(v.x); v.y = tf32r(v.y); v.z = tf32r(v.z); v.w = tf32r(v.w);
        *(float4*)(dst + (size_t)off * 4) = v;
    }
}

// ---------------------------------------------------------------------------
// Tensor-core GEMM: C[4096, NC] = X[4096,512] @ W[512,NC].
// Tile 128x128, 256 threads (8 warps 2x4), k-chunk 32, cp.async 2-stage.
// A-fragments via LDS.64 (permuted k storage). EPI=0: QKV scatter. EPI=1: store.
// ---------------------------------------------------------------------------
#define SA 40
#define SB 132
#define XS_W (128 * SA)
#define WS_W (32 * SB)
#define GEMM_SMEM ((2 * XS_W + 2 * WS_W) * 4)

template <int NC, int EPI>
__global__ __launch_bounds__(256) void gemm_tc(const float* __restrict__ Xbase,
                                               const float* __restrict__ Wbase,
                                               float* __restrict__ out) {
    extern __shared__ unsigned sh[];
    unsigned* Xs = sh;                  // 2 stages
    unsigned* Ws = sh + 2 * XS_W;

    const int mod = blockIdx.z;
    const float* __restrict__ X = Xbase + (size_t)mod * 4096 * 512;
    const float* __restrict__ W = Wbase + (size_t)mod * 512 * NC;

    const int tid = threadIdx.x;
    const int wid = tid >> 5, lane = tid & 31;
    const int grp = lane >> 2, l4 = lane & 3;
    const int wm = wid >> 2, wn = wid & 3;
    const int rowbase = blockIdx.y * 128;
    const int colbase = blockIdx.x * 128;

    float c[4][4][4];
#pragma unroll
    for (int mt = 0; mt < 4; mt++)
#pragma unroll
        for (int nt = 0; nt < 4; nt++)
#pragma unroll
            for (int e = 0; e < 4; e++) c[mt][nt][e] = 0.f;

    const int xr = tid >> 3, xc = (tid & 7) << 2;      // +32 rows per i
    const int wr = tid >> 5, wc = (tid & 31) << 2;     // +8 rows per i

    auto ldg_async = [&](int stage, int k0) {
        unsigned* Xst = Xs + stage * XS_W;
        unsigned* Wst = Ws + stage * WS_W;
#pragma unroll
        for (int i = 0; i < 4; i++) {
            cpa16(&Xst[(xr + i * 32) * SA + xc],
                  X + (size_t)(rowbase + xr + i * 32) * 512 + k0 + xc);
            cpa16(&Wst[(wr + i * 8) * SB + wc],
                  W + (size_t)(k0 + wr + i * 8) * NC + colbase + wc);
        }
    };

    ldg_async(0, 0);
    CP_COMMIT;

    for (int chunk = 0; chunk < 16; chunk++) {
        if (chunk < 15) {
            ldg_async((chunk + 1) & 1, (chunk + 1) * 32);
            CP_COMMIT;
            CP_WAIT1;
        } else {
            CP_WAIT0;
        }
        __syncthreads();

        const unsigned* Xst = Xs + (chunk & 1) * XS_W;
        const unsigned* Wst = Ws + (chunk & 1) * WS_W;
#pragma unroll
        for (int k8 = 0; k8 < 4; k8++) {
            unsigned a[4][4];
#pragma unroll
            for (int mt = 0; mt < 4; mt++) {
                int r0 = wm * 64 + mt * 16 + grp;
                uint2 p0 = *(const uint2*)&Xst[r0 * SA + k8 * 8 + l4 * 2];
                uint2 p1 = *(const uint2*)&Xst[(r0 + 8) * SA + k8 * 8 + l4 * 2];
                a[mt][0] = p0.x; a[mt][2] = p0.y;
                a[mt][1] = p1.x; a[mt][3] = p1.y;
            }
#pragma unroll
            for (int nt = 0; nt < 4; nt++) {
                unsigned b[2];
                int col = wn * 32 + nt * 8 + grp;
                b[0] = Wst[(k8 * 8 + l4) * SB + col];
                b[1] = Wst[(k8 * 8 + l4 + 4) * SB + col];
#pragma unroll
                for (int mt = 0; mt < 4; mt++) mma8(c[mt][nt], a[mt], b);
            }
        }
        __syncthreads();
    }

    // Epilogue
#pragma unroll
    for (int mt = 0; mt < 4; mt++) {
        int gr0 = rowbase + wm * 64 + mt * 16 + grp;
        int gr1 = gr0 + 8;
#pragma unroll
        for (int nt = 0; nt < 4; nt++) {
            int gc = colbase + wn * 32 + nt * 8 + l4 * 2;
            if (EPI == 1) {
                *(float2*)(out + ((size_t)mod * 4096 + gr0) * 512 + gc) =
                    make_float2(c[mt][nt][0], c[mt][nt][1]);
                *(float2*)(out + ((size_t)mod * 4096 + gr1) * 512 + gc) =
                    make_float2(c[mt][nt][2], c[mt][nt][3]);
            } else {
#pragma unroll
                for (int e = 0; e < 4; e++) {
                    int gr = (e < 2) ? gr0 : gr1;
                    int gcc = gc + (e & 1);
                    float v = c[mt][nt][e];
                    int b = gr >> 9, n = gr & 511;
                    if (gcc < 512) {
                        int h = gcc >> 6, dd = gcc & 63;
                        int pd = (dd & ~7) | perm8(dd & 7);
                        g_Q[((((size_t)mod * BB + b) * HH + h) * NN + n) * DH + pd] =
                            tf32r(v * SCALE);
                    } else if (gcc < 1024) {
                        int c2 = gcc - 512, h = c2 >> 6, dd = c2 & 63;
                        int pd = (dd & ~7) | perm8(dd & 7);
                        g_K[(((size_t)b * HH + h) * N3 + mod * NN + n) * DH + pd] = tf32r(v);
                    } else {
                        int c2 = gcc - 1024, h = c2 >> 6, dd = c2 & 63;
                        int key = mod * NN + n;
                        int pk = (key & ~7) | perm8(key & 7);
                        g_VT[(((size_t)b * HH + h) * DH + dd) * N3 + pk] = tf32r(v);
                    }
                }
            }
        }
    }
}

// ---------------------------------------------------------------------------
// Tensor-core flash attention. grid (8 qtiles of 64, 64 bh, 3 mod), 128 thr.
// K [key][perm d], V^T [d][perm key] in smem; fragments via LDS.64.
// ---------------------------------------------------------------------------
#define SK 72
#define SV 72
#define KS_W (64 * SK)
#define VS_W (64 * SV)
#define ATT_SMEM ((2 * KS_W + 2 * VS_W) * 4)

__global__ __launch_bounds__(128, 3) void attn_tc(const int* __restrict__ m0,
                                                  const int* __restrict__ m1,
                                                  const int* __restrict__ m2) {
    extern __shared__ unsigned sh[];
    unsigned* Ks = sh;
    unsigned* Vs = sh + 2 * KS_W;

    const int mod = blockIdx.z;
    const int bh = blockIdx.y;
    const int b = bh >> 3, h = bh & 7;
    const int qt = blockIdx.x;                // 64-row q tile
    const int tid = threadIdx.x;
    const int wid = tid >> 5, lane = tid & 31;
    const int grp = lane >> 2, l4 = lane & 3;

    const int* __restrict__ M = (mod == 0) ? m0 : (mod == 1) ? m1 : m2;

    const int r0 = wid * 16 + grp;            // within 64-row q tile
    const int r1 = r0 + 8;
    const bool on0 = (M[b * NN + qt * 64 + r0] != 0);
    const bool on1 = (M[b * NN + qt * 64 + r1] != 0);

    // Q A-fragments (g_Q tf32-exact, pre-scaled, perm-d) via float2
    const float* Qg = g_Q + ((((size_t)mod * BB + b) * HH + h) * NN + qt * 64) * DH;
    unsigned qa[8][4];
#pragma unroll
    for (int k8 = 0; k8 < 8; k8++) {
        float2 p0 = *(const float2*)(Qg + r0 * 64 + k8 * 8 + l4 * 2);
        float2 p1 = *(const float2*)(Qg + r1 * 64 + k8 * 8 + l4 * 2);
        qa[k8][0] = __float_as_uint(p0.x);
        qa[k8][2] = __float_as_uint(p0.y);
        qa[k8][1] = __float_as_uint(p1.x);
        qa[k8][3] = __float_as_uint(p1.y);
    }

    float m_0 = -1e30f, m_1 = -1e30f, l_0 = 0.f, l_1 = 0.f;
    float o[8][4];
#pragma unroll
    for (int nt = 0; nt < 8; nt++)
#pragma unroll
        for (int e = 0; e < 4; e++) o[nt][e] = 0.f;

    const float* Kg = g_K + (size_t)bh * N3 * DH;
    const float* VTg = g_VT + (size_t)bh * DH * N3;

    auto ldkv_async = [&](int stage, int kt) {
        unsigned* Kst = Ks + stage * KS_W;
        unsigned* Vst = Vs + stage * VS_W;
#pragma unroll
        for (int i = 0; i < 8; i++) {
            int v = tid + i * 128;
            int r = v >> 4, c4 = (v & 15) << 2;
            cpa16(&Kst[r * SK + c4], Kg + (size_t)(kt * 64 + r) * 64 + c4);
            cpa16(&Vst[r * SV + c4], VTg + (size_t)r * N3 + kt * 64 + c4);
        }
    };

    ldkv_async(0, 0);
    CP_COMMIT;

    for (int kt = 0; kt < 24; kt++) {
        if (kt < 23) {
            ldkv_async((kt + 1) & 1, kt + 1);
            CP_COMMIT;
            CP_WAIT1;
        } else {
            CP_WAIT0;
        }
        __syncthreads();

        const unsigned* Kst = Ks + (kt & 1) * KS_W;
        const unsigned* Vst = Vs + (kt & 1) * VS_W;

        // S = Q K^T
        float s[8][4];
#pragma unroll
        for (int nt = 0; nt < 8; nt++)
#pragma unroll
            for (int e = 0; e < 4; e++) s[nt][e] = 0.f;
#pragma unroll
        for (int k8 = 0; k8 < 8; k8++) {
#pragma unroll
            for (int nt = 0; nt < 8; nt++) {
                int key = nt * 8 + grp;
                uint2 bp = *(const uint2*)&Kst[key * SK + k8 * 8 + l4 * 2];
                unsigned bf[2] = {bp.x, bp.y};
                mma8(s[nt], qa[k8], bf);
            }
        }

        // Masked-row substitution
        if (!on0) {
#pragma unroll
            for (int nt = 0; nt < 8; nt++) { s[nt][0] = NEGV; s[nt][1] = NEGV; }
        }
        if (!on1) {
#pragma unroll
            for (int nt = 0; nt < 8; nt++) { s[nt][2] = NEGV; s[nt][3] = NEGV; }
        }

        // Online softmax
        float mx0 = NEGV, mx1 = NEGV;
#pragma unroll
        for (int nt = 0; nt < 8; nt++) {
            mx0 = fmaxf(mx0, fmaxf(s[nt][0], s[nt][1]));
            mx1 = fmaxf(mx1, fmaxf(s[nt][2], s[nt][3]));
        }
        mx0 = fmaxf(mx0, __shfl_xor_sync(0xffffffffu, mx0, 1));
        mx0 = fmaxf(mx0, __shfl_xor_sync(0xffffffffu, mx0, 2));
        mx1 = fmaxf(mx1, __shfl_xor_sync(0xffffffffu, mx1, 1));
        mx1 = fmaxf(mx1, __shfl_xor_sync(0xffffffffu, mx1, 2));

        float mn0 = fmaxf(m_0, mx0), mn1 = fmaxf(m_1, mx1);
        float al0 = __expf(m_0 - mn0), al1 = __expf(m_1 - mn1);
        m_0 = mn0; m_1 = mn1;

        float sum0 = 0.f, sum1 = 0.f;
#pragma unroll
        for (int nt = 0; nt < 8; nt++) {
            s[nt][0] = __expf(s[nt][0] - mn0);
            s[nt][1] = __expf(s[nt][1] - mn0);
            s[nt][2] = __expf(s[nt][2] - mn1);
            s[nt][3] = __expf(s[nt][3] - mn1);
            sum0 += s[nt][0] + s[nt][1];
            sum1 += s[nt][2] + s[nt][3];
        }
        sum0 += __shfl_xor_sync(0xffffffffu, sum0, 1);
        sum0 += __shfl_xor_sync(0xffffffffu, sum0, 2);
        sum1 += __shfl_xor_sync(0xffffffffu, sum1, 1);
        sum1 += __shfl_xor_sync(0xffffffffu, sum1, 2);
        l_0 = l_0 * al0 + sum0;
        l_1 = l_1 * al1 + sum1;

#pragma unroll
        for (int nt = 0; nt < 8; nt++) {
            o[nt][0] *= al0; o[nt][1] *= al0;
            o[nt][2] *= al1; o[nt][3] *= al1;
        }

        // O += P @ V  (C-frag -> A-frag via quad shuffles; V^T frags LDS.64)
        const int src = (grp << 2) | (l4 >> 1);
        const bool odd = (l4 & 1);
#pragma unroll
        for (int k8 = 0; k8 < 8; k8++) {
            float t0 = __shfl_sync(0xffffffffu, s[k8][0], src);
            float t1 = __shfl_sync(0xffffffffu, s[k8][1], src);
            float t2 = __shfl_sync(0xffffffffu, s[k8][2], src);
            float t3 = __shfl_sync(0xffffffffu, s[k8][3], src);
            float u0 = __shfl_sync(0xffffffffu, s[k8][0], src + 2);
            float u1 = __shfl_sync(0xffffffffu, s[k8][1], src + 2);
            float u2 = __shfl_sync(0xffffffffu, s[k8][2], src + 2);
            float u3 = __shfl_sync(0xffffffffu, s[k8][3], src + 2);
            unsigned pa[4];
            pa[0] = f2t(odd ? t1 : t0);
            pa[1] = f2t(odd ? t3 : t2);
            pa[2] = f2t(odd ? u1 : u0);
            pa[3] = f2t(odd ? u3 : u2);
#pragma unroll
            for (int nt = 0; nt < 8; nt++) {
                int drow = nt * 8 + grp;
                uint2 bp = *(const uint2*)&Vst[drow * SV + k8 * 8 + l4 * 2];
                unsigned bf[2] = {bp.x, bp.y};
                mma8(o[nt], pa, bf);
            }
        }
        __syncthreads();
    }

    // Epilogue: normalize, tf32-round, write g_O with perm-d storage
    float linv0 = 1.f / l_0, linv1 = 1.f / l_1;
    size_t base0 = (((size_t)mod * BB + b) * NN + qt * 64 + r0) * DI + h * 64;
    size_t base1 = (((size_t)mod * BB + b) * NN + qt * 64 + r1) * DI + h * 64;
    const int pd0 = perm8(2 * l4);       // in-block perm of col 2*l4
    const int pd1 = perm8(2 * l4 + 1);
#pragma unroll
    for (int nt = 0; nt < 8; nt++) {
        g_O[base0 + nt * 8 + pd0] = tf32r(o[nt][0] * linv0);
        g_O[base0 + nt * 8 + pd1] = tf32r(o[nt][1] * linv0);
        g_O[base1 + nt * 8 + pd0] = tf32r(o[nt][2] * linv1);
        g_O[base1 + nt * 8 + pd1] = tf32r(o[nt][3] * linv1);
    }
}

// ---------------------------------------------------------------------------
// Input order: 0:x0 1:m0 2:Wqkv0 3:Wout0 | 4:x1 5:m1 6:Wqkv1 7:Wout1 | 8:...
// ---------------------------------------------------------------------------
extern "C" void kernel_launch(void* const* d_in, const int* in_sizes, int n_in,
                              void* d_out, int out_size) {
    const float* x0  = (const float*)d_in[0];
    const int*   m0  = (const int*)d_in[1];
    const float* wq0 = (const float*)d_in[2];
    const float* wo0 = (const float*)d_in[3];
    const float* x1  = (const float*)d_in[4];
    const int*   m1  = (const int*)d_in[5];
    const float* wq1 = (const float*)d_in[6];
    const float* wo1 = (const float*)d_in[7];
    const float* x2  = (const float*)d_in[8];
    const int*   m2  = (const int*)d_in[9];
    const float* wq2 = (const float*)d_in[10];
    const float* wo2 = (const float*)d_in[11];
    float* out = (float*)d_out;

    static int configured = 0;
    if (!configured) {
        cudaFuncSetAttribute(gemm_tc<1536, 0>,
                             cudaFuncAttributeMaxDynamicSharedMemorySize, GEMM_SMEM);
        cudaFuncSetAttribute(gemm_tc<512, 1>,
                             cudaFuncAttributeMaxDynamicSharedMemorySize, GEMM_SMEM);
        cudaFuncSetAttribute(attn_tc,
                             cudaFuncAttributeMaxDynamicSharedMemorySize, ATT_SMEM);
        configured = 1;
    }

    float *gx, *gwq, *gwo, *go;
    cudaGetSymbolAddress((void**)&gx, g_X);
    cudaGetSymbolAddress((void**)&gwq, g_Wq);
    cudaGetSymbolAddress((void**)&gwo, g_Wo);
    cudaGetSymbolAddress((void**)&go, g_O);

    prep_round<<<dim3(3072, 3), 256>>>(x0, wq0, wo0, x1, wq1, wo1, x2, wq2, wo2);
    gemm_tc<1536, 0><<<dim3(12, 32, 3), 256, GEMM_SMEM>>>(gx, gwq, nullptr);
    attn_tc<<<dim3(8, 64, 3), 128, ATT_SMEM>>>(m0, m1, m2);
    gemm_tc<512, 1><<<dim3(4, 32, 3), 256, GEMM_SMEM>>>(go, gwo, out);
}

// round 8
// speedup vs baseline: 4.0502x; 1.0079x over previous
#include <cuda_runtime.h>
#include <math.h>
#include <stdint.h>

#define BB 8
#define NN 512
#define HH 8
#define DH 64
#define DI 512
#define N3 1536
#define SCALE 0.125f
#define NEGV -1e9f

// Scratch (device globals). All tf32-exact fp32 bits.
// k-dims stored with in-block perm8 so mma fragment pairs (k, k+4) are adjacent.
__device__ float g_X[3ull * 4096 * 512];           // [mod][row][perm k]
__device__ float g_WqT[3ull * 1536 * 512];         // [mod][n][perm k]  (transposed)
__device__ float g_WoT[3ull * 512 * 512];          // [mod][n][perm k]  (transposed)
__device__ float g_Q[3ull * BB * HH * NN * DH];    // [mod][b][h][n][perm d], pre-scaled
__device__ float g_K[(size_t)BB * HH * N3 * DH];   // [bh][key][perm d]
__device__ float g_VT[(size_t)BB * HH * DH * N3];  // [bh][d][perm key]
__device__ float g_O[3ull * BB * NN * DI];         // [mod][b][n][perm (h*64+d)]

__device__ __forceinline__ int perm8(int j) { return ((j & 3) << 1) | (j >> 2); }

__device__ __forceinline__ unsigned f2t(float f) {
    unsigned u;
    asm("cvt.rna.tf32.f32 %0, %1;" : "=r"(u) : "f"(f));
    return u;
}
__device__ __forceinline__ float tf32r(float f) { return __uint_as_float(f2t(f)); }

__device__ __forceinline__ void mma8(float d[4], const unsigned a[4], const unsigned b[2]) {
    asm volatile(
        "mma.sync.aligned.m16n8k8.row.col.f32.tf32.tf32.f32 "
        "{%0,%1,%2,%3}, {%4,%5,%6,%7}, {%8,%9}, {%0,%1,%2,%3};"
        : "+f"(d[0]), "+f"(d[1]), "+f"(d[2]), "+f"(d[3])
        : "r"(a[0]), "r"(a[1]), "r"(a[2]), "r"(a[3]), "r"(b[0]), "r"(b[1]));
}

__device__ __forceinline__ void cpa16(unsigned* dst, const float* src) {
    unsigned d = (unsigned)__cvta_generic_to_shared(dst);
    asm volatile("cp.async.cg.shared.global [%0], [%1], 16;\n" ::"r"(d), "l"(src));
}
#define CP_COMMIT asm volatile("cp.async.commit_group;\n" ::)
#define CP_WAIT1 asm volatile("cp.async.wait_group 1;\n" ::)
#define CP_WAIT0 asm volatile("cp.async.wait_group 0;\n" ::)

// ---------------------------------------------------------------------------
// Prep: X tf32-round + perm8 columns. grid (2048, 3), 256 threads.
// ---------------------------------------------------------------------------
__global__ void prep_x(const float* __restrict__ x0, const float* __restrict__ x1,
                       const float* __restrict__ x2) {
    const int mod = blockIdx.y;
    const float* __restrict__ X = (mod == 0) ? x0 : (mod == 1) ? x1 : x2;
    int i = blockIdx.x * 256 + threadIdx.x;   // float4 index
    int o = i * 4;
    int row = o >> 9, c = o & 511;
    int base = c & ~7;
    float v[4];
#pragma unroll
    for (int q = 0; q < 4; q++) {
        int qq = (c + q) & 7;
        int j = ((qq & 1) << 2) | (qq >> 1);     // inverse perm
        v[q] = tf32r(X[(size_t)row * 512 + base + j]);
    }
    *(float4*)(g_X + (size_t)mod * 4096 * 512 + o) = make_float4(v[0], v[1], v[2], v[3]);
}

// Transpose W [512][N] -> WT [mod][N][512], tf32-rounded, perm8 on k.
__global__ void transpose_w(const float* __restrict__ w0, const float* __restrict__ w1,
                            const float* __restrict__ w2, float* __restrict__ dst,
                            int N) {
    __shared__ float t[32][33];
    const int mod = blockIdx.z;
    const float* __restrict__ W = (mod == 0) ? w0 : (mod == 1) ? w1 : w2;
    float* __restrict__ D = dst + (size_t)mod * N * 512;
    const int n0 = blockIdx.x * 32, k0 = blockIdx.y * 32;
    const int tx = threadIdx.x, ty = threadIdx.y;
#pragma unroll
    for (int j = ty; j < 32; j += 8) t[j][tx] = W[(size_t)(k0 + j) * N + n0 + tx];
    __syncthreads();
#pragma unroll
    for (int j = ty; j < 32; j += 8) {
        int pk = (tx & ~7) | perm8(tx & 7);
        D[(size_t)(n0 + j) * 512 + k0 + pk] = tf32r(t[tx][j]);
    }
}

// ---------------------------------------------------------------------------
// Tensor-core GEMM: C[4096, NC] = X[4096,512] @ W[512,NC]  (W given as WT[n][k]).
// Tile 128x128, 256 threads (8 warps 2x4), k-chunk 32, cp.async 2-stage.
// BOTH fragments via LDS.64 (perm8 k storage, both operands k-contiguous).
// EPI=0: QKV scatter epilogue.  EPI=1: direct fp32 store to out.
// ---------------------------------------------------------------------------
#define SA 40
#define SBT 40
#define XS_W (128 * SA)
#define WS_W (128 * SBT)
#define GEMM_SMEM ((2 * XS_W + 2 * WS_W) * 4)

template <int NC, int EPI>
__global__ __launch_bounds__(256) void gemm_tc(const float* __restrict__ Xbase,
                                               const float* __restrict__ WTbase,
                                               float* __restrict__ out) {
    extern __shared__ unsigned sh[];
    unsigned* Xs = sh;                  // 2 stages
    unsigned* Ws = sh + 2 * XS_W;

    const int mod = blockIdx.z;
    const float* __restrict__ X = Xbase + (size_t)mod * 4096 * 512;
    const float* __restrict__ WT = WTbase + (size_t)mod * NC * 512;

    const int tid = threadIdx.x;
    const int wid = tid >> 5, lane = tid & 31;
    const int grp = lane >> 2, l4 = lane & 3;
    const int wm = wid >> 2, wn = wid & 3;
    const int rowbase = blockIdx.y * 128;
    const int colbase = blockIdx.x * 128;

    float c[4][4][4];
#pragma unroll
    for (int mt = 0; mt < 4; mt++)
#pragma unroll
        for (int nt = 0; nt < 4; nt++)
#pragma unroll
            for (int e = 0; e < 4; e++) c[mt][nt][e] = 0.f;

    const int rr = tid >> 3, cc = (tid & 7) << 2;      // 128 rows x 8 chunks; +32 rows per i

    auto ldg_async = [&](int stage, int k0) {
        unsigned* Xst = Xs + stage * XS_W;
        unsigned* Wst = Ws + stage * WS_W;
#pragma unroll
        for (int i = 0; i < 4; i++) {
            cpa16(&Xst[(rr + i * 32) * SA + cc],
                  X + (size_t)(rowbase + rr + i * 32) * 512 + k0 + cc);
            cpa16(&Wst[(rr + i * 32) * SBT + cc],
                  WT + (size_t)(colbase + rr + i * 32) * 512 + k0 + cc);
        }
    };

    ldg_async(0, 0);
    CP_COMMIT;

    for (int chunk = 0; chunk < 16; chunk++) {
        if (chunk < 15) {
            ldg_async((chunk + 1) & 1, (chunk + 1) * 32);
            CP_COMMIT;
            CP_WAIT1;
        } else {
            CP_WAIT0;
        }
        __syncthreads();

        const unsigned* Xst = Xs + (chunk & 1) * XS_W;
        const unsigned* Wst = Ws + (chunk & 1) * WS_W;
#pragma unroll
        for (int k8 = 0; k8 < 4; k8++) {
            unsigned a[4][4];
#pragma unroll
            for (int mt = 0; mt < 4; mt++) {
                int r0 = wm * 64 + mt * 16 + grp;
                uint2 p0 = *(const uint2*)&Xst[r0 * SA + k8 * 8 + l4 * 2];
                uint2 p1 = *(const uint2*)&Xst[(r0 + 8) * SA + k8 * 8 + l4 * 2];
                a[mt][0] = p0.x; a[mt][2] = p0.y;
                a[mt][1] = p1.x; a[mt][3] = p1.y;
            }
#pragma unroll
            for (int nt = 0; nt < 4; nt++) {
                int col = wn * 32 + nt * 8 + grp;
                uint2 bp = *(const uint2*)&Wst[col * SBT + k8 * 8 + l4 * 2];
                unsigned b[2] = {bp.x, bp.y};
#pragma unroll
                for (int mt = 0; mt < 4; mt++) mma8(c[mt][nt], a[mt], b);
            }
        }
        __syncthreads();
    }

    // Epilogue
#pragma unroll
    for (int mt = 0; mt < 4; mt++) {
        int gr0 = rowbase + wm * 64 + mt * 16 + grp;
        int gr1 = gr0 + 8;
#pragma unroll
        for (int nt = 0; nt < 4; nt++) {
            int gc = colbase + wn * 32 + nt * 8 + l4 * 2;
            if (EPI == 1) {
                *(float2*)(out + ((size_t)mod * 4096 + gr0) * 512 + gc) =
                    make_float2(c[mt][nt][0], c[mt][nt][1]);
                *(float2*)(out + ((size_t)mod * 4096 + gr1) * 512 + gc) =
                    make_float2(c[mt][nt][2], c[mt][nt][3]);
            } else {
#pragma unroll
                for (int e = 0; e < 4; e++) {
                    int gr = (e < 2) ? gr0 : gr1;
                    int gcc = gc + (e & 1);
                    float v = c[mt][nt][e];
                    int b = gr >> 9, n = gr & 511;
                    if (gcc < 512) {
                        int h = gcc >> 6, dd = gcc & 63;
                        int pd = (dd & ~7) | perm8(dd & 7);
                        g_Q[((((size_t)mod * BB + b) * HH + h) * NN + n) * DH + pd] =
                            tf32r(v * SCALE);
                    } else if (gcc < 1024) {
                        int c2 = gcc - 512, h = c2 >> 6, dd = c2 & 63;
                        int pd = (dd & ~7) | perm8(dd & 7);
                        g_K[(((size_t)b * HH + h) * N3 + mod * NN + n) * DH + pd] = tf32r(v);
                    } else {
                        int c2 = gcc - 1024, h = c2 >> 6, dd = c2 & 63;
                        int key = mod * NN + n;
                        int pk = (key & ~7) | perm8(key & 7);
                        g_VT[(((size_t)b * HH + h) * DH + dd) * N3 + pk] = tf32r(v);
                    }
                }
            }
        }
    }
}

// ---------------------------------------------------------------------------
// Tensor-core flash attention. grid (8 qtiles of 64, 64 bh, 3 mod), 128 thr.
// K [key][perm d], V^T [d][perm key] in smem; fragments via LDS.64.
// ---------------------------------------------------------------------------
#define SK 72
#define SV 72
#define KS_W (64 * SK)
#define VS_W (64 * SV)
#define ATT_SMEM ((2 * KS_W + 2 * VS_W) * 4)

__global__ __launch_bounds__(128, 3) void attn_tc(const int* __restrict__ m0,
                                                  const int* __restrict__ m1,
                                                  const int* __restrict__ m2) {
    extern __shared__ unsigned sh[];
    unsigned* Ks = sh;
    unsigned* Vs = sh + 2 * KS_W;

    const int mod = blockIdx.z;
    const int bh = blockIdx.y;
    const int b = bh >> 3, h = bh & 7;
    const int qt = blockIdx.x;                // 64-row q tile
    const int tid = threadIdx.x;
    const int wid = tid >> 5, lane = tid & 31;
    const int grp = lane >> 2, l4 = lane & 3;

    const int* __restrict__ M = (mod == 0) ? m0 : (mod == 1) ? m1 : m2;

    const int r0 = wid * 16 + grp;            // within 64-row q tile
    const int r1 = r0 + 8;
    const bool on0 = (M[b * NN + qt * 64 + r0] != 0);
    const bool on1 = (M[b * NN + qt * 64 + r1] != 0);

    // Q A-fragments (g_Q tf32-exact, pre-scaled, perm-d) via float2
    const float* Qg = g_Q + ((((size_t)mod * BB + b) * HH + h) * NN + qt * 64) * DH;
    unsigned qa[8][4];
#pragma unroll
    for (int k8 = 0; k8 < 8; k8++) {
        float2 p0 = *(const float2*)(Qg + r0 * 64 + k8 * 8 + l4 * 2);
        float2 p1 = *(const float2*)(Qg + r1 * 64 + k8 * 8 + l4 * 2);
        qa[k8][0] = __float_as_uint(p0.x);
        qa[k8][2] = __float_as_uint(p0.y);
        qa[k8][1] = __float_as_uint(p1.x);
        qa[k8][3] = __float_as_uint(p1.y);
    }

    float m_0 = -1e30f, m_1 = -1e30f, l_0 = 0.f, l_1 = 0.f;
    float o[8][4];
#pragma unroll
    for (int nt = 0; nt < 8; nt++)
#pragma unroll
        for (int e = 0; e < 4; e++) o[nt][e] = 0.f;

    const float* Kg = g_K + (size_t)bh * N3 * DH;
    const float* VTg = g_VT + (size_t)bh * DH * N3;

    auto ldkv_async = [&](int stage, int kt) {
        unsigned* Kst = Ks + stage * KS_W;
        unsigned* Vst = Vs + stage * VS_W;
#pragma unroll
        for (int i = 0; i < 8; i++) {
            int v = tid + i * 128;
            int r = v >> 4, c4 = (v & 15) << 2;
            cpa16(&Kst[r * SK + c4], Kg + (size_t)(kt * 64 + r) * 64 + c4);
            cpa16(&Vst[r * SV + c4], VTg + (size_t)r * N3 + kt * 64 + c4);
        }
    };

    ldkv_async(0, 0);
    CP_COMMIT;

    for (int kt = 0; kt < 24; kt++) {
        if (kt < 23) {
            ldkv_async((kt + 1) & 1, kt + 1);
            CP_COMMIT;
            CP_WAIT1;
        } else {
            CP_WAIT0;
        }
        __syncthreads();

        const unsigned* Kst = Ks + (kt & 1) * KS_W;
        const unsigned* Vst = Vs + (kt & 1) * VS_W;

        // S = Q K^T
        float s[8][4];
#pragma unroll
        for (int nt = 0; nt < 8; nt++)
#pragma unroll
            for (int e = 0; e < 4; e++) s[nt][e] = 0.f;
#pragma unroll
        for (int k8 = 0; k8 < 8; k8++) {
#pragma unroll
            for (int nt = 0; nt < 8; nt++) {
                int key = nt * 8 + grp;
                uint2 bp = *(const uint2*)&Kst[key * SK + k8 * 8 + l4 * 2];
                unsigned bf[2] = {bp.x, bp.y};
                mma8(s[nt], qa[k8], bf);
            }
        }

        // Masked-row substitution
        if (!on0) {
#pragma unroll
            for (int nt = 0; nt < 8; nt++) { s[nt][0] = NEGV; s[nt][1] = NEGV; }
        }
        if (!on1) {
#pragma unroll
            for (int nt = 0; nt < 8; nt++) { s[nt][2] = NEGV; s[nt][3] = NEGV; }
        }

        // Online softmax
        float mx0 = NEGV, mx1 = NEGV;
#pragma unroll
        for (int nt = 0; nt < 8; nt++) {
            mx0 = fmaxf(mx0, fmaxf(s[nt][0], s[nt][1]));
            mx1 = fmaxf(mx1, fmaxf(s[nt][2], s[nt][3]));
        }
        mx0 = fmaxf(mx0, __shfl_xor_sync(0xffffffffu, mx0, 1));
        mx0 = fmaxf(mx0, __shfl_xor_sync(0xffffffffu, mx0, 2));
        mx1 = fmaxf(mx1, __shfl_xor_sync(0xffffffffu, mx1, 1));
        mx1 = fmaxf(mx1, __shfl_xor_sync(0xffffffffu, mx1, 2));

        float mn0 = fmaxf(m_0, mx0), mn1 = fmaxf(m_1, mx1);
        float al0 = __expf(m_0 - mn0), al1 = __expf(m_1 - mn1);
        m_0 = mn0; m_1 = mn1;

        float sum0 = 0.f, sum1 = 0.f;
#pragma unroll
        for (int nt = 0; nt < 8; nt++) {
            s[nt][0] = __expf(s[nt][0] - mn0);
            s[nt][1] = __expf(s[nt][1] - mn0);
            s[nt][2] = __expf(s[nt][2] - mn1);
            s[nt][3] = __expf(s[nt][3] - mn1);
            sum0 += s[nt][0] + s[nt][1];
            sum1 += s[nt][2] + s[nt][3];
        }
        sum0 += __shfl_xor_sync(0xffffffffu, sum0, 1);
        sum0 += __shfl_xor_sync(0xffffffffu, sum0, 2);
        sum1 += __shfl_xor_sync(0xffffffffu, sum1, 1);
        sum1 += __shfl_xor_sync(0xffffffffu, sum1, 2);
        l_0 = l_0 * al0 + sum0;
        l_1 = l_1 * al1 + sum1;

#pragma unroll
        for (int nt = 0; nt < 8; nt++) {
            o[nt][0] *= al0; o[nt][1] *= al0;
            o[nt][2] *= al1; o[nt][3] *= al1;
        }

        // O += P @ V  (C-frag -> A-frag via quad shuffles; V^T frags LDS.64)
        const int src = (grp << 2) | (l4 >> 1);
        const bool odd = (l4 & 1);
#pragma unroll
        for (int k8 = 0; k8 < 8; k8++) {
            float t0 = __shfl_sync(0xffffffffu, s[k8][0], src);
            float t1 = __shfl_sync(0xffffffffu, s[k8][1], src);
            float t2 = __shfl_sync(0xffffffffu, s[k8][2], src);
            float t3 = __shfl_sync(0xffffffffu, s[k8][3], src);
            float u0 = __shfl_sync(0xffffffffu, s[k8][0], src + 2);
            float u1 = __shfl_sync(0xffffffffu, s[k8][1], src + 2);
            float u2 = __shfl_sync(0xffffffffu, s[k8][2], src + 2);
            float u3 = __shfl_sync(0xffffffffu, s[k8][3], src + 2);
            unsigned pa[4];
            pa[0] = f2t(odd ? t1 : t0);
            pa[1] = f2t(odd ? t3 : t2);
            pa[2] = f2t(odd ? u1 : u0);
            pa[3] = f2t(odd ? u3 : u2);
#pragma unroll
            for (int nt = 0; nt < 8; nt++) {
                int drow = nt * 8 + grp;
                uint2 bp = *(const uint2*)&Vst[drow * SV + k8 * 8 + l4 * 2];
                unsigned bf[2] = {bp.x, bp.y};
                mma8(o[nt], pa, bf);
            }
        }
        __syncthreads();
    }

    // Epilogue: normalize, tf32-round, write g_O with perm-d storage
    float linv0 = 1.f / l_0, linv1 = 1.f / l_1;
    size_t base0 = (((size_t)mod * BB + b) * NN + qt * 64 + r0) * DI + h * 64;
    size_t base1 = (((size_t)mod * BB + b) * NN + qt * 64 + r1) * DI + h * 64;
    const int pd0 = perm8(2 * l4);
    const int pd1 = perm8(2 * l4 + 1);
#pragma unroll
    for (int nt = 0; nt < 8; nt++) {
        g_O[base0 + nt * 8 + pd0] = tf32r(o[nt][0] * linv0);
        g_O[base0 + nt * 8 + pd1] = tf32r(o[nt][1] * linv0);
        g_O[base1 + nt * 8 + pd0] = tf32r(o[nt][2] * linv1);
        g_O[base1 + nt * 8 + pd1] = tf32r(o[nt][3] * linv1);
    }
}

// ---------------------------------------------------------------------------
// Input order: 0:x0 1:m0 2:Wqkv0 3:Wout0 | 4:x1 5:m1 6:Wqkv1 7:Wout1 | 8:...
// ---------------------------------------------------------------------------
extern "C" void kernel_launch(void* const* d_in, const int* in_sizes, int n_in,
                              void* d_out, int out_size) {
    const float* x0  = (const float*)d_in[0];
    const int*   m0  = (const int*)d_in[1];
    const float* wq0 = (const float*)d_in[2];
    const float* wo0 = (const float*)d_in[3];
    const float* x1  = (const float*)d_in[4];
    const int*   m1  = (const int*)d_in[5];
    const float* wq1 = (const float*)d_in[6];
    const float* wo1 = (const float*)d_in[7];
    const float* x2  = (const float*)d_in[8];
    const int*   m2  = (const int*)d_in[9];
    const float* wq2 = (const float*)d_in[10];
    const float* wo2 = (const float*)d_in[11];
    float* out = (float*)d_out;

    static int configured = 0;
    if (!configured) {
        cudaFuncSetAttribute(gemm_tc<1536, 0>,
                             cudaFuncAttributeMaxDynamicSharedMemorySize, GEMM_SMEM);
        cudaFuncSetAttribute(gemm_tc<512, 1>,
                             cudaFuncAttributeMaxDynamicSharedMemorySize, GEMM_SMEM);
        cudaFuncSetAttribute(attn_tc,
                             cudaFuncAttributeMaxDynamicSharedMemorySize, ATT_SMEM);
        configured = 1;
    }

    float *gx, *gwqt, *gwot, *go;
    cudaGetSymbolAddress((void**)&gx, g_X);
    cudaGetSymbolAddress((void**)&gwqt, g_WqT);
    cudaGetSymbolAddress((void**)&gwot, g_WoT);
    cudaGetSymbolAddress((void**)&go, g_O);

    prep_x<<<dim3(2048, 3), 256>>>(x0, x1, x2);
    transpose_w<<<dim3(48, 16, 3), dim3(32, 8)>>>(wq0, wq1, wq2, gwqt, 1536);
    transpose_w<<<dim3(16, 16, 3), dim3(32, 8)>>>(wo0, wo1, wo2, gwot, 512);
    gemm_tc<1536, 0><<<dim3(12, 32, 3), 256, GEMM_SMEM>>>(gx, gwqt, nullptr);
    attn_tc<<<dim3(8, 64, 3), 128, ATT_SMEM>>>(m0, m1, m2);
    gemm_tc<512, 1><<<dim3(4, 32, 3), 256, GEMM_SMEM>>>(go, gwot, out);
}

// round 9
// speedup vs baseline: 4.6190x; 1.1404x over previous
#include <cuda_runtime.h>
#include <math.h>
#include <stdint.h>

#define BB 8
#define NN 512
#define HH 8
#define DH 64
#define DI 512
#define N3 1536
#define SCALE 0.125f

// Scratch (device globals). All tf32-exact fp32 bits.
// k-dims stored with in-block perm8 so mma fragment pairs (k, k+4) are adjacent.
__device__ float g_X[3ull * 4096 * 512];           // [mod][row][perm k]
__device__ float g_WqT[3ull * 1536 * 512];         // [mod][n][perm k]
__device__ float g_WoT[3ull * 512 * 512];          // [mod][n][perm k]
__device__ float g_Q[3ull * BB * HH * NN * DH];    // [mod][b][h][n][perm d], pre-scaled
__device__ float g_K[(size_t)BB * HH * N3 * DH];   // [bh][key][perm d]
__device__ float g_VT[(size_t)BB * HH * DH * N3];  // [bh][d][perm key]
__device__ float g_O[3ull * BB * NN * DI];         // [mod][b][n][perm (h*64+d)]
__device__ int   g_idx[24 * 512];                  // unmasked row indices per (mod,b)
__device__ int   g_cnt[24];
__device__ float g_meanV[64 * 64];                 // [bh][d]

__device__ __forceinline__ int perm8(int j) { return ((j & 3) << 1) | (j >> 2); }

__device__ __forceinline__ unsigned f2t(float f) {
    unsigned u;
    asm("cvt.rna.tf32.f32 %0, %1;" : "=r"(u) : "f"(f));
    return u;
}
__device__ __forceinline__ float tf32r(float f) { return __uint_as_float(f2t(f)); }

__device__ __forceinline__ void mma8(float d[4], const unsigned a[4], const unsigned b[2]) {
    asm volatile(
        "mma.sync.aligned.m16n8k8.row.col.f32.tf32.tf32.f32 "
        "{%0,%1,%2,%3}, {%4,%5,%6,%7}, {%8,%9}, {%0,%1,%2,%3};"
        : "+f"(d[0]), "+f"(d[1]), "+f"(d[2]), "+f"(d[3])
        : "r"(a[0]), "r"(a[1]), "r"(a[2]), "r"(a[3]), "r"(b[0]), "r"(b[1]));
}

__device__ __forceinline__ void cpa16(unsigned* dst, const float* src) {
    unsigned d = (unsigned)__cvta_generic_to_shared(dst);
    asm volatile("cp.async.cg.shared.global [%0], [%1], 16;\n" ::"r"(d), "l"(src));
}
#define CP_COMMIT asm volatile("cp.async.commit_group;\n" ::)
#define CP_WAIT1 asm volatile("cp.async.wait_group 1;\n" ::)
#define CP_WAIT0 asm volatile("cp.async.wait_group 0;\n" ::)

// ---------------------------------------------------------------------------
// Prep: X tf32-round + perm8 columns. grid (2048, 3), 256 threads.
// ---------------------------------------------------------------------------
__global__ void prep_x(const float* __restrict__ x0, const float* __restrict__ x1,
                       const float* __restrict__ x2) {
    const int mod = blockIdx.y;
    const float* __restrict__ X = (mod == 0) ? x0 : (mod == 1) ? x1 : x2;
    int i = blockIdx.x * 256 + threadIdx.x;
    int o = i * 4;
    int row = o >> 9, c = o & 511;
    int base = c & ~7;
    float v[4];
#pragma unroll
    for (int q = 0; q < 4; q++) {
        int qq = (c + q) & 7;
        int j = ((qq & 1) << 2) | (qq >> 1);     // inverse perm
        v[q] = tf32r(X[(size_t)row * 512 + base + j]);
    }
    *(float4*)(g_X + (size_t)mod * 4096 * 512 + o) = make_float4(v[0], v[1], v[2], v[3]);
}

// Transpose W [512][N] -> WT [mod][N][512], tf32-rounded, perm8 on k.
__global__ void transpose_w(const float* __restrict__ w0, const float* __restrict__ w1,
                            const float* __restrict__ w2, float* __restrict__ dst,
                            int N) {
    __shared__ float t[32][33];
    const int mod = blockIdx.z;
    const float* __restrict__ W = (mod == 0) ? w0 : (mod == 1) ? w1 : w2;
    float* __restrict__ D = dst + (size_t)mod * N * 512;
    const int n0 = blockIdx.x * 32, k0 = blockIdx.y * 32;
    const int tx = threadIdx.x, ty = threadIdx.y;
#pragma unroll
    for (int j = ty; j < 32; j += 8) t[j][tx] = W[(size_t)(k0 + j) * N + n0 + tx];
    __syncthreads();
#pragma unroll
    for (int j = ty; j < 32; j += 8) {
        int pk = (tx & ~7) | perm8(tx & 7);
        D[(size_t)(n0 + j) * 512 + k0 + pk] = tf32r(t[tx][j]);
    }
}

// ---------------------------------------------------------------------------
// Mask compaction: per (mod,b) build list of unmasked row indices + count.
// grid 24, 512 threads.
// ---------------------------------------------------------------------------
__global__ void compact_mask(const int* __restrict__ m0, const int* __restrict__ m1,
                             const int* __restrict__ m2) {
    const int mb = blockIdx.x;
    const int mod = mb >> 3, b = mb & 7;
    const int* __restrict__ M = (mod == 0) ? m0 : (mod == 1) ? m1 : m2;
    const int tid = threadIdx.x;
    const int on = (M[b * NN + tid] != 0) ? 1 : 0;
    const int lane = tid & 31, w = tid >> 5;
    unsigned ball = __ballot_sync(0xffffffffu, on);
    int pre = __popc(ball & ((1u << lane) - 1u));
    __shared__ int wsum[16];
    if (lane == 31) wsum[w] = pre + on;
    __syncthreads();
    if (tid == 0) {
        int acc = 0;
#pragma unroll
        for (int i = 0; i < 16; i++) { int t = wsum[i]; wsum[i] = acc; acc += t; }
        g_cnt[mb] = acc;
    }
    __syncthreads();
    if (on) g_idx[mb * 512 + wsum[w] + pre] = tid;
}

// ---------------------------------------------------------------------------
// meanV: per bh, mean over all 1536 keys of V (rows of g_VT; perm-invariant).
// grid 64, 128 threads (2 per d).
// ---------------------------------------------------------------------------
__global__ void mean_v() {
    const int bh = blockIdx.x;
    const int d = threadIdx.x >> 1, half = threadIdx.x & 1;
    const float* row = g_VT + (size_t)bh * DH * N3 + (size_t)d * N3 + half * 768;
    float s = 0.f;
#pragma unroll 4
    for (int i = 0; i < 768; i += 4) {
        float4 v = *(const float4*)(row + i);
        s += v.x + v.y + v.z + v.w;
    }
    s += __shfl_xor_sync(0xffffffffu, s, 1);
    if (!half) g_meanV[bh * 64 + d] = s * (1.0f / 1536.0f);
}

// ---------------------------------------------------------------------------
// fill_masked: masked rows of g_O <- meanV (tf32-rounded, perm8-stored).
// grid 24, 256 threads.
// ---------------------------------------------------------------------------
__global__ void fill_masked(const int* __restrict__ m0, const int* __restrict__ m1,
                            const int* __restrict__ m2) {
    const int mb = blockIdx.x;
    const int mod = mb >> 3, b = mb & 7;
    const int* __restrict__ M = (mod == 0) ? m0 : (mod == 1) ? m1 : m2;
    const int tid = threadIdx.x;
    const int c0 = tid * 2, c1 = c0 + 1;
    const float v0 = tf32r(g_meanV[(b * HH + (c0 >> 6)) * 64 + (c0 & 63)]);
    const float v1 = tf32r(g_meanV[(b * HH + (c1 >> 6)) * 64 + (c1 & 63)]);
    const int pc0 = (c0 & ~7) | perm8(c0 & 7);
    const int pc1 = (c1 & ~7) | perm8(c1 & 7);
    float* base = g_O + ((size_t)mb * NN) * DI;
    for (int n = 0; n < NN; n++) {
        if (M[b * NN + n] == 0) {
            float* row = base + (size_t)n * DI;
            row[pc0] = v0;
            row[pc1] = v1;
        }
    }
}

// ---------------------------------------------------------------------------
// Tensor-core GEMM: C[4096, NC] = X[4096,512] @ W[512,NC]  (W given as WT[n][k]).
// Tile 128x128, 256 threads (8 warps 2x4), k-chunk 32, cp.async 2-stage.
// BOTH fragments via LDS.64. EPI=0: QKV scatter. EPI=1: direct store.
// ---------------------------------------------------------------------------
#define SA 40
#define SBT 40
#define XS_W (128 * SA)
#define WS_W (128 * SBT)
#define GEMM_SMEM ((2 * XS_W + 2 * WS_W) * 4)

template <int NC, int EPI>
__global__ __launch_bounds__(256) void gemm_tc(const float* __restrict__ Xbase,
                                               const float* __restrict__ WTbase,
                                               float* __restrict__ out) {
    extern __shared__ unsigned sh[];
    unsigned* Xs = sh;
    unsigned* Ws = sh + 2 * XS_W;

    const int mod = blockIdx.z;
    const float* __restrict__ X = Xbase + (size_t)mod * 4096 * 512;
    const float* __restrict__ WT = WTbase + (size_t)mod * NC * 512;

    const int tid = threadIdx.x;
    const int wid = tid >> 5, lane = tid & 31;
    const int grp = lane >> 2, l4 = lane & 3;
    const int wm = wid >> 2, wn = wid & 3;
    const int rowbase = blockIdx.y * 128;
    const int colbase = blockIdx.x * 128;

    float c[4][4][4];
#pragma unroll
    for (int mt = 0; mt < 4; mt++)
#pragma unroll
        for (int nt = 0; nt < 4; nt++)
#pragma unroll
            for (int e = 0; e < 4; e++) c[mt][nt][e] = 0.f;

    const int rr = tid >> 3, cc = (tid & 7) << 2;

    auto ldg_async = [&](int stage, int k0) {
        unsigned* Xst = Xs + stage * XS_W;
        unsigned* Wst = Ws + stage * WS_W;
#pragma unroll
        for (int i = 0; i < 4; i++) {
            cpa16(&Xst[(rr + i * 32) * SA + cc],
                  X + (size_t)(rowbase + rr + i * 32) * 512 + k0 + cc);
            cpa16(&Wst[(rr + i * 32) * SBT + cc],
                  WT + (size_t)(colbase + rr + i * 32) * 512 + k0 + cc);
        }
    };

    ldg_async(0, 0);
    CP_COMMIT;

    for (int chunk = 0; chunk < 16; chunk++) {
        if (chunk < 15) {
            ldg_async((chunk + 1) & 1, (chunk + 1) * 32);
            CP_COMMIT;
            CP_WAIT1;
        } else {
            CP_WAIT0;
        }
        __syncthreads();

        const unsigned* Xst = Xs + (chunk & 1) * XS_W;
        const unsigned* Wst = Ws + (chunk & 1) * WS_W;
#pragma unroll
        for (int k8 = 0; k8 < 4; k8++) {
            unsigned a[4][4];
#pragma unroll
            for (int mt = 0; mt < 4; mt++) {
                int r0 = wm * 64 + mt * 16 + grp;
                uint2 p0 = *(const uint2*)&Xst[r0 * SA + k8 * 8 + l4 * 2];
                uint2 p1 = *(const uint2*)&Xst[(r0 + 8) * SA + k8 * 8 + l4 * 2];
                a[mt][0] = p0.x; a[mt][2] = p0.y;
                a[mt][1] = p1.x; a[mt][3] = p1.y;
            }
#pragma unroll
            for (int nt = 0; nt < 4; nt++) {
                int col = wn * 32 + nt * 8 + grp;
                uint2 bp = *(const uint2*)&Wst[col * SBT + k8 * 8 + l4 * 2];
                unsigned b[2] = {bp.x, bp.y};
#pragma unroll
                for (int mt = 0; mt < 4; mt++) mma8(c[mt][nt], a[mt], b);
            }
        }
        __syncthreads();
    }

    // Epilogue
#pragma unroll
    for (int mt = 0; mt < 4; mt++) {
        int gr0 = rowbase + wm * 64 + mt * 16 + grp;
        int gr1 = gr0 + 8;
#pragma unroll
        for (int nt = 0; nt < 4; nt++) {
            int gc = colbase + wn * 32 + nt * 8 + l4 * 2;
            if (EPI == 1) {
                *(float2*)(out + ((size_t)mod * 4096 + gr0) * 512 + gc) =
                    make_float2(c[mt][nt][0], c[mt][nt][1]);
                *(float2*)(out + ((size_t)mod * 4096 + gr1) * 512 + gc) =
                    make_float2(c[mt][nt][2], c[mt][nt][3]);
            } else {
#pragma unroll
                for (int e = 0; e < 4; e++) {
                    int gr = (e < 2) ? gr0 : gr1;
                    int gcc = gc + (e & 1);
                    float v = c[mt][nt][e];
                    int b = gr >> 9, n = gr & 511;
                    if (gcc < 512) {
                        int h = gcc >> 6, dd = gcc & 63;
                        int pd = (dd & ~7) | perm8(dd & 7);
                        g_Q[((((size_t)mod * BB + b) * HH + h) * NN + n) * DH + pd] =
                            tf32r(v * SCALE);
                    } else if (gcc < 1024) {
                        int c2 = gcc - 512, h = c2 >> 6, dd = c2 & 63;
                        int pd = (dd & ~7) | perm8(dd & 7);
                        g_K[(((size_t)b * HH + h) * N3 + mod * NN + n) * DH + pd] = tf32r(v);
                    } else {
                        int c2 = gcc - 1024, h = c2 >> 6, dd = c2 & 63;
                        int key = mod * NN + n;
                        int pk = (key & ~7) | perm8(key & 7);
                        g_VT[(((size_t)b * HH + h) * DH + dd) * N3 + pk] = tf32r(v);
                    }
                }
            }
        }
    }
}

// ---------------------------------------------------------------------------
// Flash attention over COMPACTED (unmasked) query rows only.
// grid (8 qtiles of 64, 64 bh, 3 mod), 128 thr. Blocks past cnt exit early.
// ---------------------------------------------------------------------------
#define SK 72
#define SV 72
#define KS_W (64 * SK)
#define VS_W (64 * SV)
#define ATT_SMEM ((2 * KS_W + 2 * VS_W) * 4)

__global__ __launch_bounds__(128, 3) void attn_tc() {
    extern __shared__ unsigned sh[];
    unsigned* Ks = sh;
    unsigned* Vs = sh + 2 * KS_W;

    const int mod = blockIdx.z;
    const int bh = blockIdx.y;
    const int b = bh >> 3, h = bh & 7;
    const int qt = blockIdx.x;
    const int mb = mod * 8 + b;

    const int cnt = g_cnt[mb];
    if (qt * 64 >= cnt) return;

    const int tid = threadIdx.x;
    const int wid = tid >> 5, lane = tid & 31;
    const int grp = lane >> 2, l4 = lane & 3;

    const int r0 = wid * 16 + grp;            // within 64-row compacted tile
    const int r1 = r0 + 8;
    const int gr0 = qt * 64 + r0, gr1 = qt * 64 + r1;
    const int gmax = cnt - 1;
    const int* idxp = g_idx + mb * 512;
    const int i0 = idxp[min(gr0, gmax)];
    const int i1 = idxp[min(gr1, gmax)];

    // Q A-fragments (gathered rows; tf32-exact, pre-scaled, perm-d)
    const float* Qg = g_Q + (((size_t)mb * HH + h) * NN) * DH;
    unsigned qa[8][4];
#pragma unroll
    for (int k8 = 0; k8 < 8; k8++) {
        float2 p0 = *(const float2*)(Qg + (size_t)i0 * 64 + k8 * 8 + l4 * 2);
        float2 p1 = *(const float2*)(Qg + (size_t)i1 * 64 + k8 * 8 + l4 * 2);
        qa[k8][0] = __float_as_uint(p0.x);
        qa[k8][2] = __float_as_uint(p0.y);
        qa[k8][1] = __float_as_uint(p1.x);
        qa[k8][3] = __float_as_uint(p1.y);
    }

    float m_0 = -1e30f, m_1 = -1e30f, l_0 = 0.f, l_1 = 0.f;
    float o[8][4];
#pragma unroll
    for (int nt = 0; nt < 8; nt++)
#pragma unroll
        for (int e = 0; e < 4; e++) o[nt][e] = 0.f;

    const float* Kg = g_K + (size_t)bh * N3 * DH;
    const float* VTg = g_VT + (size_t)bh * DH * N3;

    auto ldkv_async = [&](int stage, int kt) {
        unsigned* Kst = Ks + stage * KS_W;
        unsigned* Vst = Vs + stage * VS_W;
#pragma unroll
        for (int i = 0; i < 8; i++) {
            int v = tid + i * 128;
            int r = v >> 4, c4 = (v & 15) << 2;
            cpa16(&Kst[r * SK + c4], Kg + (size_t)(kt * 64 + r) * 64 + c4);
            cpa16(&Vst[r * SV + c4], VTg + (size_t)r * N3 + kt * 64 + c4);
        }
    };

    ldkv_async(0, 0);
    CP_COMMIT;

    for (int kt = 0; kt < 24; kt++) {
        if (kt < 23) {
            ldkv_async((kt + 1) & 1, kt + 1);
            CP_COMMIT;
            CP_WAIT1;
        } else {
            CP_WAIT0;
        }
        __syncthreads();

        const unsigned* Kst = Ks + (kt & 1) * KS_W;
        const unsigned* Vst = Vs + (kt & 1) * VS_W;

        // S = Q K^T
        float s[8][4];
#pragma unroll
        for (int nt = 0; nt < 8; nt++)
#pragma unroll
            for (int e = 0; e < 4; e++) s[nt][e] = 0.f;
#pragma unroll
        for (int k8 = 0; k8 < 8; k8++) {
#pragma unroll
            for (int nt = 0; nt < 8; nt++) {
                int key = nt * 8 + grp;
                uint2 bp = *(const uint2*)&Kst[key * SK + k8 * 8 + l4 * 2];
                unsigned bf[2] = {bp.x, bp.y};
                mma8(s[nt], qa[k8], bf);
            }
        }

        // Online softmax (no masking: all rows unmasked)
        float mx0 = -1e30f, mx1 = -1e30f;
#pragma unroll
        for (int nt = 0; nt < 8; nt++) {
            mx0 = fmaxf(mx0, fmaxf(s[nt][0], s[nt][1]));
            mx1 = fmaxf(mx1, fmaxf(s[nt][2], s[nt][3]));
        }
        mx0 = fmaxf(mx0, __shfl_xor_sync(0xffffffffu, mx0, 1));
        mx0 = fmaxf(mx0, __shfl_xor_sync(0xffffffffu, mx0, 2));
        mx1 = fmaxf(mx1, __shfl_xor_sync(0xffffffffu, mx1, 1));
        mx1 = fmaxf(mx1, __shfl_xor_sync(0xffffffffu, mx1, 2));

        float mn0 = fmaxf(m_0, mx0), mn1 = fmaxf(m_1, mx1);
        float al0 = __expf(m_0 - mn0), al1 = __expf(m_1 - mn1);
        m_0 = mn0; m_1 = mn1;

        float sum0 = 0.f, sum1 = 0.f;
#pragma unroll
        for (int nt = 0; nt < 8; nt++) {
            s[nt][0] = __expf(s[nt][0] - mn0);
            s[nt][1] = __expf(s[nt][1] - mn0);
            s[nt][2] = __expf(s[nt][2] - mn1);
            s[nt][3] = __expf(s[nt][3] - mn1);
            sum0 += s[nt][0] + s[nt][1];
            sum1 += s[nt][2] + s[nt][3];
        }
        sum0 += __shfl_xor_sync(0xffffffffu, sum0, 1);
        sum0 += __shfl_xor_sync(0xffffffffu, sum0, 2);
        sum1 += __shfl_xor_sync(0xffffffffu, sum1, 1);
        sum1 += __shfl_xor_sync(0xffffffffu, sum1, 2);
        l_0 = l_0 * al0 + sum0;
        l_1 = l_1 * al1 + sum1;

#pragma unroll
        for (int nt = 0; nt < 8; nt++) {
            o[nt][0] *= al0; o[nt][1] *= al0;
            o[nt][2] *= al1; o[nt][3] *= al1;
        }

        // O += P @ V  (C-frag -> A-frag via quad shuffles; V^T frags LDS.64)
        const int src = (grp << 2) | (l4 >> 1);
        const bool odd = (l4 & 1);
#pragma unroll
        for (int k8 = 0; k8 < 8; k8++) {
            float t0 = __shfl_sync(0xffffffffu, s[k8][0], src);
            float t1 = __shfl_sync(0xffffffffu, s[k8][1], src);
            float t2 = __shfl_sync(0xffffffffu, s[k8][2], src);
            float t3 = __shfl_sync(0xffffffffu, s[k8][3], src);
            float u0 = __shfl_sync(0xffffffffu, s[k8][0], src + 2);
            float u1 = __shfl_sync(0xffffffffu, s[k8][1], src + 2);
            float u2 = __shfl_sync(0xffffffffu, s[k8][2], src + 2);
            float u3 = __shfl_sync(0xffffffffu, s[k8][3], src + 2);
            unsigned pa[4];
            pa[0] = f2t(odd ? t1 : t0);
            pa[1] = f2t(odd ? t3 : t2);
            pa[2] = f2t(odd ? u1 : u0);
            pa[3] = f2t(odd ? u3 : u2);
#pragma unroll
            for (int nt = 0; nt < 8; nt++) {
                int drow = nt * 8 + grp;
                uint2 bp = *(const uint2*)&Vst[drow * SV + k8 * 8 + l4 * 2];
                unsigned bf[2] = {bp.x, bp.y};
                mma8(o[nt], pa, bf);
            }
        }
        __syncthreads();
    }

    // Epilogue: normalize, tf32-round, scatter to original rows (perm-d cols)
    float linv0 = 1.f / l_0, linv1 = 1.f / l_1;
    size_t base0 = ((size_t)mb * NN + i0) * DI + h * 64;
    size_t base1 = ((size_t)mb * NN + i1) * DI + h * 64;
    const int pd0 = perm8(2 * l4);
    const int pd1 = perm8(2 * l4 + 1);
    if (gr0 < cnt) {
#pragma unroll
        for (int nt = 0; nt < 8; nt++) {
            g_O[base0 + nt * 8 + pd0] = tf32r(o[nt][0] * linv0);
            g_O[base0 + nt * 8 + pd1] = tf32r(o[nt][1] * linv0);
        }
    }
    if (gr1 < cnt) {
#pragma unroll
        for (int nt = 0; nt < 8; nt++) {
            g_O[base1 + nt * 8 + pd0] = tf32r(o[nt][2] * linv1);
            g_O[base1 + nt * 8 + pd1] = tf32r(o[nt][3] * linv1);
        }
    }
}

// ---------------------------------------------------------------------------
// Input order: 0:x0 1:m0 2:Wqkv0 3:Wout0 | 4:x1 5:m1 6:Wqkv1 7:Wout1 | 8:...
// ---------------------------------------------------------------------------
extern "C" void kernel_launch(void* const* d_in, const int* in_sizes, int n_in,
                              void* d_out, int out_size) {
    const float* x0  = (const float*)d_in[0];
    const int*   m0  = (const int*)d_in[1];
    const float* wq0 = (const float*)d_in[2];
    const float* wo0 = (const float*)d_in[3];
    const float* x1  = (const float*)d_in[4];
    const int*   m1  = (const int*)d_in[5];
    const float* wq1 = (const float*)d_in[6];
    const float* wo1 = (const float*)d_in[7];
    const float* x2  = (const float*)d_in[8];
    const int*   m2  = (const int*)d_in[9];
    const float* wq2 = (const float*)d_in[10];
    const float* wo2 = (const float*)d_in[11];
    float* out = (float*)d_out;

    static int configured = 0;
    if (!configured) {
        cudaFuncSetAttribute(gemm_tc<1536, 0>,
                             cudaFuncAttributeMaxDynamicSharedMemorySize, GEMM_SMEM);
        cudaFuncSetAttribute(gemm_tc<512, 1>,
                             cudaFuncAttributeMaxDynamicSharedMemorySize, GEMM_SMEM);
        cudaFuncSetAttribute(attn_tc,
                             cudaFuncAttributeMaxDynamicSharedMemorySize, ATT_SMEM);
        configured = 1;
    }

    float *gx, *gwqt, *gwot, *go;
    cudaGetSymbolAddress((void**)&gx, g_X);
    cudaGetSymbolAddress((void**)&gwqt, g_WqT);
    cudaGetSymbolAddress((void**)&gwot, g_WoT);
    cudaGetSymbolAddress((void**)&go, g_O);

    prep_x<<<dim3(2048, 3), 256>>>(x0, x1, x2);
    transpose_w<<<dim3(48, 16, 3), dim3(32, 8)>>>(wq0, wq1, wq2, gwqt, 1536);
    transpose_w<<<dim3(16, 16, 3), dim3(32, 8)>>>(wo0, wo1, wo2, gwot, 512);
    compact_mask<<<24, 512>>>(m0, m1, m2);
    gemm_tc<1536, 0><<<dim3(12, 32, 3), 256, GEMM_SMEM>>>(gx, gwqt, nullptr);
    mean_v<<<64, 128>>>();
    fill_masked<<<24, 256>>>(m0, m1, m2);
    attn_tc<<<dim3(8, 64, 3), 128, ATT_SMEM>>>();
    gemm_tc<512, 1><<<dim3(4, 32, 3), 256, GEMM_SMEM>>>(go, gwot, out);
}